// round 14
// baseline (speedup 1.0000x reference)
#include <cuda_runtime.h>
#include <cuda_bf16.h>
#include <math.h>
#include <stdint.h>

#define NN 50000
#define TT 8
#define HH 128
#define EE 800000
#define NBLK 49   // scan blocks of 1024

// ---------------- scratch (device globals; no allocation allowed) ----------
__device__ __align__(16) float g_h0a[NN * HH];
__device__ __align__(16) float g_h0b[NN * HH];
__device__ __align__(16) float g_h1a[NN * HH];
__device__ __align__(16) float g_h1b[NN * HH];
__device__ __align__(16) float g_hs[NN * HH];
__device__ __align__(16) float g_cur[NN * HH];
__device__ __align__(16) float g_cur2[NN * HH];
__device__ __align__(16) float g_u[NN * HH];
__device__ __align__(16) float g_r[NN * HH];     // holds r*h_prev (f32)
__device__ int   g_deg[NN];
__device__ int   g_rowptr[NN + 1];
__device__ int   g_cursor[NN];
__device__ int   g_csrc[EE];
__device__ float g_dinv[NN];
__device__ int   g_bsum[64];
__device__ int   g_boff[64];

// transposed + hi/lo-split weights, [N rows, K cols] bf16
#define WT_TOTAL 278528
__device__ __align__(16) __nv_bfloat16 g_wt_hi[WT_TOTAL];
__device__ __align__(16) __nv_bfloat16 g_wt_lo[WT_TOTAL];

// WU/WR pairs contiguous: [Wu rows 0-127 | Wr rows 128-255], K=256
#define OFF_WIN0 0
#define OFF_WH0  16384
#define OFF_WU0  32768
#define OFF_WR0  65536
#define OFF_WC0  98304
#define OFF_WIN1 131072
#define OFF_WH1  147456
#define OFF_WU1  163840
#define OFF_WR1  196608
#define OFF_WC1  229376
#define OFF_WOUT 262144

// ---------------- warp-mma helpers (baseline PTX, no arch suffix) -----------
__device__ __forceinline__ uint32_t smem_u32(const void* p) {
    uint32_t a;
    asm("{ .reg .u64 t; cvta.to.shared.u64 t, %1; cvt.u32.u64 %0, t; }" : "=r"(a) : "l"(p));
    return a;
}
__device__ __forceinline__ void ldsm4(uint32_t& r0, uint32_t& r1, uint32_t& r2, uint32_t& r3,
                                      uint32_t addr) {
    asm volatile("ldmatrix.sync.aligned.m8n8.x4.shared.b16 {%0,%1,%2,%3}, [%4];"
                 : "=r"(r0), "=r"(r1), "=r"(r2), "=r"(r3) : "r"(addr));
}
__device__ __forceinline__ void mma_bf16(float* d, const uint32_t* a, const uint32_t* b) {
    asm volatile(
        "mma.sync.aligned.m16n8k16.row.col.f32.bf16.bf16.f32 "
        "{%0,%1,%2,%3},{%4,%5,%6,%7},{%8,%9},{%0,%1,%2,%3};"
        : "+f"(d[0]), "+f"(d[1]), "+f"(d[2]), "+f"(d[3])
        : "r"(a[0]), "r"(a[1]), "r"(a[2]), "r"(a[3]), "r"(b[0]), "r"(b[1]));
}

// ---------------- small utility kernels ------------------------------------
__global__ void zero_f_kernel(float* p, int n) {
    for (int i = blockIdx.x * blockDim.x + threadIdx.x; i < n; i += gridDim.x * blockDim.x)
        p[i] = 0.0f;
}
__global__ void zero_deg_kernel(int n) {
    for (int i = blockIdx.x * blockDim.x + threadIdx.x; i < n; i += gridDim.x * blockDim.x)
        g_deg[i] = 0;
}
__global__ void hist_kernel(const int* __restrict__ dst, int e) {
    for (int i = blockIdx.x * blockDim.x + threadIdx.x; i < e; i += gridDim.x * blockDim.x)
        atomicAdd(&g_deg[dst[i]], 1);
}

// scan phase A: per-block exclusive scan of deg; partial rowptr + dinv + block sums
__global__ __launch_bounds__(1024) void scan_a_kernel(int n) {
    __shared__ int wsum[32];
    const int lane = threadIdx.x & 31;
    const int wid  = threadIdx.x >> 5;
    const int i = blockIdx.x * 1024 + threadIdx.x;
    int v = (i < n) ? g_deg[i] : 0;
    int incl = v;
    #pragma unroll
    for (int off = 1; off < 32; off <<= 1) {
        int t = __shfl_up_sync(0xffffffffu, incl, off);
        if (lane >= off) incl += t;
    }
    if (lane == 31) wsum[wid] = incl;
    __syncthreads();
    if (wid == 0) {
        int w = wsum[lane];
        #pragma unroll
        for (int off = 1; off < 32; off <<= 1) {
            int t = __shfl_up_sync(0xffffffffu, w, off);
            if (lane >= off) w += t;
        }
        wsum[lane] = w;
    }
    __syncthreads();
    int excl = (incl - v) + (wid > 0 ? wsum[wid - 1] : 0);
    if (i < n) {
        g_rowptr[i] = excl;
        g_dinv[i]   = rsqrtf((float)v + 1.0f);
    }
    if (threadIdx.x == 1023) g_bsum[blockIdx.x] = excl + v;
}

// scan phase B: exclusive scan of NBLK block sums (single block, 64 threads)
__global__ void scan_b_kernel(int n) {
    __shared__ int sh[64];
    const int tid = threadIdx.x;
    const int lane = tid & 31;
    const int w = tid >> 5;
    int v = (tid < NBLK) ? g_bsum[tid] : 0;
    int incl = v;
    #pragma unroll
    for (int off = 1; off < 32; off <<= 1) {
        int t = __shfl_up_sync(0xffffffffu, incl, off);
        if (lane >= off) incl += t;
    }
    if (lane == 31) sh[w] = incl;
    __syncthreads();
    int base = (w == 1) ? sh[0] : 0;
    incl += base;
    if (tid < NBLK) g_boff[tid] = incl - v;
    if (tid == NBLK - 1) g_rowptr[n] = incl;
}

// scan phase C: add block offsets, init cursor
__global__ __launch_bounds__(1024) void scan_c_kernel(int n) {
    const int i = blockIdx.x * 1024 + threadIdx.x;
    if (i < n) {
        int r = g_rowptr[i] + g_boff[blockIdx.x];
        g_rowptr[i] = r;
        g_cursor[i] = r;
    }
}

__global__ void fill_kernel(const int* __restrict__ src, const int* __restrict__ dst, int e) {
    for (int i = blockIdx.x * blockDim.x + threadIdx.x; i < e; i += gridDim.x * blockDim.x) {
        int slot = atomicAdd(&g_cursor[dst[i]], 1);
        g_csrc[slot] = src[i];
    }
}

// warp-per-node gather: lane handles 4 features (float4).
__global__ __launch_bounds__(256) void gather_kernel(
    const float* __restrict__ hs, const float* __restrict__ bias,
    float* __restrict__ out, int relu) {
    const int wid = threadIdx.x >> 5;
    const int lane = threadIdx.x & 31;
    const int node = blockIdx.x * 8 + wid;
    const int beg = g_rowptr[node];
    const int end = g_rowptr[node + 1];
    const float dn = g_dinv[node];
    const float4* hs4 = (const float4*)hs;
    const size_t fo = (size_t)node * 32 + lane;

    float4 a = hs4[fo];
    float4 acc = make_float4(dn * a.x, dn * a.y, dn * a.z, dn * a.w);
    int j = beg;
    for (; j + 4 <= end; j += 4) {
        int s0 = g_csrc[j], s1 = g_csrc[j + 1], s2 = g_csrc[j + 2], s3 = g_csrc[j + 3];
        float d0 = g_dinv[s0], d1 = g_dinv[s1], d2 = g_dinv[s2], d3 = g_dinv[s3];
        float4 v0 = hs4[(size_t)s0 * 32 + lane];
        float4 v1 = hs4[(size_t)s1 * 32 + lane];
        float4 v2 = hs4[(size_t)s2 * 32 + lane];
        float4 v3 = hs4[(size_t)s3 * 32 + lane];
        acc.x += d0 * v0.x + d1 * v1.x + d2 * v2.x + d3 * v3.x;
        acc.y += d0 * v0.y + d1 * v1.y + d2 * v2.y + d3 * v3.y;
        acc.z += d0 * v0.z + d1 * v1.z + d2 * v2.z + d3 * v3.z;
        acc.w += d0 * v0.w + d1 * v1.w + d2 * v2.w + d3 * v3.w;
    }
    for (; j < end; ++j) {
        int s = g_csrc[j];
        float d = g_dinv[s];
        float4 v = hs4[(size_t)s * 32 + lane];
        acc.x += d * v.x; acc.y += d * v.y; acc.z += d * v.z; acc.w += d * v.w;
    }
    float4 b = ((const float4*)bias)[lane];
    float4 r;
    r.x = dn * acc.x + b.x;
    r.y = dn * acc.y + b.y;
    r.z = dn * acc.z + b.z;
    r.w = dn * acc.w + b.w;
    if (relu) {
        r.x = fmaxf(r.x, 0.0f); r.y = fmaxf(r.y, 0.0f);
        r.z = fmaxf(r.z, 0.0f); r.w = fmaxf(r.w, 0.0f);
    }
    ((float4*)out)[fo] = r;
}

// weight prep: src [K,128] f32 row-major -> dst [128,K] bf16 hi/lo (transposed)
__global__ void prep_w_kernel(const float* __restrict__ W,
                              __nv_bfloat16* __restrict__ hi,
                              __nv_bfloat16* __restrict__ lo, int K) {
    int total = K * 128;
    for (int idx = blockIdx.x * blockDim.x + threadIdx.x; idx < total;
         idx += gridDim.x * blockDim.x) {
        int k = idx >> 7;
        int nn = idx & 127;
        float v = W[idx];
        __nv_bfloat16 h = __float2bfloat16_rn(v);
        __nv_bfloat16 l = __float2bfloat16_rn(v - __bfloat162float(h));
        hi[(size_t)nn * K + k] = h;
        lo[(size_t)nn * K + k] = l;
    }
}

// ---------------- tensor-core GEMM via mma.sync -----------------------------
// Block tile 64(M) x 64(N), 256 threads, 8 warps of 16x32 (wm 0..3, wn 0..1).
// Small accumulator set -> 3 CTAs/SM (24 warps) for latency hiding.
// blockIdx.y: weight-row group of 64; split=1 (u|r): y>>1 picks u vs r,
// output col base = (y&1)*64.
#define EPI_NONE 0
#define EPI_SIG  1
#define EPI_GRU  2
#define EPI_BIAS 3

#define ROWB 80
#define SM_AHI 0
#define SM_ALO (64 * ROWB)                // 5120
#define SM_BHI (2 * 64 * ROWB)            // 10240
#define SM_BLO (3 * 64 * ROWB)            // 15360
#define SM_TOT (4 * 64 * ROWB)            // 20480

__global__ __launch_bounds__(256, 3) void gemm_mma_kernel(
    const float* __restrict__ A1, const float* __restrict__ A2,
    const __nv_bfloat16* __restrict__ Bt_hi, const __nv_bfloat16* __restrict__ Bt_lo,
    const float* __restrict__ bias, const float* __restrict__ bias2,
    const float* __restrict__ u, const float* __restrict__ hprev,
    float* __restrict__ out, float* __restrict__ out2,
    int n, int K, int epi, int split)
{
    extern __shared__ __align__(16) char smem[];
    const uint32_t sb = smem_u32(smem);
    const int tid = threadIdx.x;
    const int wid = tid >> 5;
    const int lane = tid & 31;
    const int row0 = blockIdx.x * 64;
    const int n0 = blockIdx.y * 64;
    const int wm = wid & 3;        // 4 m-groups of 16 rows
    const int wn = wid >> 2;       // 2 n-groups of 32 cols

    // A staging: 64 rows x 32 f32 = 512 float4 slots; thread does tid, tid+256
    const int ar0 = tid >> 3;
    const int ar1 = (tid >> 3) + 32;
    const int ac4 = (tid & 7) * 4;
    // B staging: 64 rows x 32 bf16 = 256 uint4 slots; one per thread
    const int br_ = tid >> 2;
    const int bc8 = (tid & 3) * 8;

    float acc[4][4];
    #pragma unroll
    for (int j = 0; j < 4; j++)
        #pragma unroll
        for (int q = 0; q < 4; q++) acc[j][q] = 0.0f;

    const int nc = K >> 5;
    float4 pa[2];
    uint4 pbh, pbl;

    {
        int g0 = row0 + ar0, g1 = row0 + ar1;
        pa[0] = (g0 < n) ? *(const float4*)(A1 + (size_t)g0 * 128 + ac4)
                         : make_float4(0.f, 0.f, 0.f, 0.f);
        pa[1] = (g1 < n) ? *(const float4*)(A1 + (size_t)g1 * 128 + ac4)
                         : make_float4(0.f, 0.f, 0.f, 0.f);
        size_t goff = (size_t)(n0 + br_) * K + bc8;
        pbh = *(const uint4*)(Bt_hi + goff);
        pbl = *(const uint4*)(Bt_lo + goff);
    }

    for (int c = 0; c < nc; c++) {
        #pragma unroll
        for (int it = 0; it < 2; it++) {
            float4 v = pa[it];
            int r = it ? ar1 : ar0;
            __nv_bfloat16 h0 = __float2bfloat16_rn(v.x);
            __nv_bfloat16 h1 = __float2bfloat16_rn(v.y);
            __nv_bfloat16 h2 = __float2bfloat16_rn(v.z);
            __nv_bfloat16 h3 = __float2bfloat16_rn(v.w);
            __nv_bfloat16 l0 = __float2bfloat16_rn(v.x - __bfloat162float(h0));
            __nv_bfloat16 l1 = __float2bfloat16_rn(v.y - __bfloat162float(h1));
            __nv_bfloat16 l2 = __float2bfloat16_rn(v.z - __bfloat162float(h2));
            __nv_bfloat16 l3 = __float2bfloat16_rn(v.w - __bfloat162float(h3));
            uint32_t hA = (uint32_t)__bfloat16_as_ushort(h0) |
                          ((uint32_t)__bfloat16_as_ushort(h1) << 16);
            uint32_t hB = (uint32_t)__bfloat16_as_ushort(h2) |
                          ((uint32_t)__bfloat16_as_ushort(h3) << 16);
            uint32_t lA = (uint32_t)__bfloat16_as_ushort(l0) |
                          ((uint32_t)__bfloat16_as_ushort(l1) << 16);
            uint32_t lB = (uint32_t)__bfloat16_as_ushort(l2) |
                          ((uint32_t)__bfloat16_as_ushort(l3) << 16);
            uint32_t off = r * ROWB + ac4 * 2;
            *(uint2*)(smem + SM_AHI + off) = make_uint2(hA, hB);
            *(uint2*)(smem + SM_ALO + off) = make_uint2(lA, lB);
        }
        {
            uint32_t off = br_ * ROWB + bc8 * 2;
            *(uint4*)(smem + SM_BHI + off) = pbh;
            *(uint4*)(smem + SM_BLO + off) = pbl;
        }
        __syncthreads();

        if (c + 1 < nc) {
            const int kn = (c + 1) * 32;
            const float* Asrc = (kn >= 128) ? A2 : A1;
            const int kln = (kn >= 128) ? kn - 128 : kn;
            int g0 = row0 + ar0, g1 = row0 + ar1;
            pa[0] = (g0 < n) ? *(const float4*)(Asrc + (size_t)g0 * 128 + kln + ac4)
                             : make_float4(0.f, 0.f, 0.f, 0.f);
            pa[1] = (g1 < n) ? *(const float4*)(Asrc + (size_t)g1 * 128 + kln + ac4)
                             : make_float4(0.f, 0.f, 0.f, 0.f);
            size_t goff = (size_t)(n0 + br_) * K + kn + bc8;
            pbh = *(const uint4*)(Bt_hi + goff);
            pbl = *(const uint4*)(Bt_lo + goff);
        }

        #pragma unroll
        for (int ks = 0; ks < 2; ks++) {
            uint32_t ah[4], al[4];
            {
                uint32_t addr = sb + SM_AHI +
                    (uint32_t)(wm * 16 + (lane & 15)) * ROWB +
                    ks * 32 + (lane >> 4) * 16;
                ldsm4(ah[0], ah[1], ah[2], ah[3], addr);
                ldsm4(al[0], al[1], al[2], al[3], addr + (SM_ALO - SM_AHI));
            }
            uint32_t bh0[4], bh1[4], bl0[4], bl1[4];
            {
                uint32_t baddr = sb + SM_BHI + (uint32_t)(wn * 32 + lane) * ROWB + ks * 32;
                ldsm4(bh0[0], bh0[1], bh0[2], bh0[3], baddr);
                ldsm4(bh1[0], bh1[1], bh1[2], bh1[3], baddr + 16);
                ldsm4(bl0[0], bl0[1], bl0[2], bl0[3], baddr + (SM_BLO - SM_BHI));
                ldsm4(bl1[0], bl1[1], bl1[2], bl1[3], baddr + (SM_BLO - SM_BHI) + 16);
            }
            #pragma unroll
            for (int nt = 0; nt < 4; nt++) {
                uint32_t bh[2] = {bh0[nt], bh1[nt]};
                uint32_t bl[2] = {bl0[nt], bl1[nt]};
                mma_bf16(acc[nt], ah, bh);
                mma_bf16(acc[nt], ah, bl);
                mma_bf16(acc[nt], al, bh);
            }
        }
        __syncthreads();
    }

    // ---- epilogue ----
    const int urpart = split ? (int)(blockIdx.y >> 1) : 0;
    const float* biasX = (split && urpart) ? bias2 : bias;
    float* outX = (split && urpart) ? out2 : out;
    const int ybase = (blockIdx.y & 1) * 64;
    const int qrow = lane >> 2;
    const int qcol = (lane & 3) * 2;
    const int gc_base = ybase + wn * 32;
    #pragma unroll
    for (int rs = 0; rs < 2; rs++) {
        int grow = row0 + wm * 16 + rs * 8 + qrow;
        if (grow >= n) continue;
        size_t rbase = (size_t)grow * 128;
        #pragma unroll
        for (int nt = 0; nt < 4; nt++) {
            int gc = gc_base + nt * 8 + qcol;
            float v0 = acc[nt][rs * 2];
            float v1 = acc[nt][rs * 2 + 1];
            float r0, r1;
            if (epi == EPI_NONE) {
                r0 = v0; r1 = v1;
            } else if (epi == EPI_SIG) {
                r0 = 1.0f / (1.0f + expf(-(v0 + biasX[gc])));
                r1 = 1.0f / (1.0f + expf(-(v1 + biasX[gc + 1])));
                // r-half of fused u|r: write r*h_prev -> consumed as plain A2
                if (urpart && hprev) {
                    r0 *= hprev[rbase + gc];
                    r1 *= hprev[rbase + gc + 1];
                }
            } else if (epi == EPI_GRU) {
                float a0 = tanhf(v0 + biasX[gc]);
                float a1 = tanhf(v1 + biasX[gc + 1]);
                float hp0 = hprev[rbase + gc], hp1 = hprev[rbase + gc + 1];
                float u0 = u[rbase + gc], u1 = u[rbase + gc + 1];
                r0 = hp0 + u0 * (a0 - hp0);
                r1 = hp1 + u1 * (a1 - hp1);
            } else {
                r0 = v0 + biasX[gc]; r1 = v1 + biasX[gc + 1];
            }
            *(float2*)(outX + rbase + gc) = make_float2(r0, r1);
        }
    }
}

// ---------------- driver ------------------------------------------------------
static inline void gemm_tc(const float* A1, const float* A2,
                           const __nv_bfloat16* bh, const __nv_bfloat16* bl,
                           const float* bias, const float* bias2,
                           const float* u, const float* hprev,
                           float* out, float* out2, int K, int epi, int ny, int split) {
    dim3 grid((NN + 63) / 64, ny);
    gemm_mma_kernel<<<grid, 256, SM_TOT>>>(A1, A2, bh, bl, bias, bias2,
                                           u, hprev, out, out2, NN, K, epi, split);
}

extern "C" void kernel_launch(void* const* d_in, const int* in_sizes, int n_in,
                              void* d_out, int out_size) {
    const float* x_seq = (const float*)d_in[0];
    const int*   ei    = (const int*)d_in[1];
    const float* W_in0 = (const float*)d_in[2];
    const float* b_in0 = (const float*)d_in[3];
    const float* W_h0  = (const float*)d_in[4];
    const float* b_h0  = (const float*)d_in[5];
    const float* Wu0   = (const float*)d_in[6];
    const float* bu0   = (const float*)d_in[7];
    const float* Wr0   = (const float*)d_in[8];
    const float* br0   = (const float*)d_in[9];
    const float* Wc0   = (const float*)d_in[10];
    const float* bc0   = (const float*)d_in[11];
    const float* W_in1 = (const float*)d_in[12];
    const float* b_in1 = (const float*)d_in[13];
    const float* W_h1  = (const float*)d_in[14];
    const float* b_h1  = (const float*)d_in[15];
    const float* Wu1   = (const float*)d_in[16];
    const float* bu1   = (const float*)d_in[17];
    const float* Wr1   = (const float*)d_in[18];
    const float* br1   = (const float*)d_in[19];
    const float* Wc1   = (const float*)d_in[20];
    const float* bc1   = (const float*)d_in[21];
    const float* W_out = (const float*)d_in[22];
    const float* b_out = (const float*)d_in[23];
    float* out = (float*)d_out;

    float *p_h0a, *p_h0b, *p_h1a, *p_h1b;
    float *p_hs, *p_cur, *p_cur2, *p_u, *p_r;
    __nv_bfloat16 *p_wth, *p_wtl;
    cudaGetSymbolAddress((void**)&p_h0a,  g_h0a);
    cudaGetSymbolAddress((void**)&p_h0b,  g_h0b);
    cudaGetSymbolAddress((void**)&p_h1a,  g_h1a);
    cudaGetSymbolAddress((void**)&p_h1b,  g_h1b);
    cudaGetSymbolAddress((void**)&p_hs,   g_hs);
    cudaGetSymbolAddress((void**)&p_cur,  g_cur);
    cudaGetSymbolAddress((void**)&p_cur2, g_cur2);
    cudaGetSymbolAddress((void**)&p_u,    g_u);
    cudaGetSymbolAddress((void**)&p_r,    g_r);
    cudaGetSymbolAddress((void**)&p_wth,  g_wt_hi);
    cudaGetSymbolAddress((void**)&p_wtl,  g_wt_lo);

    const int EB = (EE + 255) / 256;
    const int PB = 128;
    const int GBK = NN / 8;   // gather blocks (8 nodes/block)

    for (int t = 0; t < TT; t++) {
        float* h0r = (t & 1) ? p_h0b : p_h0a;
        float* h0w = (t & 1) ? p_h0a : p_h0b;
        float* h1r = (t & 1) ? p_h1b : p_h1a;
        float* h1w = (t & 1) ? p_h1a : p_h1b;

        const int* src = ei + (size_t)t * 2 * EE;
        const int* dst = src + EE;
        const float* xin = x_seq + (size_t)t * NN * HH;

        // t=0 launch order: zero_deg(0), hist(1), prep(2), gemm(3) <- ncu idx 3
        zero_deg_kernel<<<128, 256>>>(NN);
        hist_kernel<<<EB, 256>>>(dst, EE);
        if (t == 0)
            prep_w_kernel<<<PB, 256>>>(W_in0, p_wth + OFF_WIN0, p_wtl + OFF_WIN0, 128);
        gemm_tc(xin, nullptr, p_wth + OFF_WIN0, p_wtl + OFF_WIN0,
                nullptr, nullptr, nullptr, nullptr, p_hs, nullptr, 128, EPI_NONE, 2, 0);
        scan_a_kernel<<<NBLK, 1024>>>(NN);
        scan_b_kernel<<<1, 64>>>(NN);
        scan_c_kernel<<<NBLK, 1024>>>(NN);
        fill_kernel<<<EB, 256>>>(src, dst, EE);
        if (t == 0) {
            zero_f_kernel<<<512, 256>>>(p_h0a, NN * HH);
            zero_f_kernel<<<512, 256>>>(p_h1a, NN * HH);
            prep_w_kernel<<<PB, 256>>>(W_h0,  p_wth + OFF_WH0,  p_wtl + OFF_WH0,  128);
            prep_w_kernel<<<PB, 256>>>(Wu0,   p_wth + OFF_WU0,  p_wtl + OFF_WU0,  256);
            prep_w_kernel<<<PB, 256>>>(Wr0,   p_wth + OFF_WR0,  p_wtl + OFF_WR0,  256);
            prep_w_kernel<<<PB, 256>>>(Wc0,   p_wth + OFF_WC0,  p_wtl + OFF_WC0,  256);
            prep_w_kernel<<<PB, 256>>>(W_in1, p_wth + OFF_WIN1, p_wtl + OFF_WIN1, 128);
            prep_w_kernel<<<PB, 256>>>(W_h1,  p_wth + OFF_WH1,  p_wtl + OFF_WH1,  128);
            prep_w_kernel<<<PB, 256>>>(Wu1,   p_wth + OFF_WU1,  p_wtl + OFF_WU1,  256);
            prep_w_kernel<<<PB, 256>>>(Wr1,   p_wth + OFF_WR1,  p_wtl + OFF_WR1,  256);
            prep_w_kernel<<<PB, 256>>>(Wc1,   p_wth + OFF_WC1,  p_wtl + OFF_WC1,  256);
            prep_w_kernel<<<PB, 256>>>(W_out, p_wth + OFF_WOUT, p_wtl + OFF_WOUT, 128);
        }

        // ---- layer 0 cell (state h0r -> h0w) ----
        gather_kernel<<<GBK, 256>>>(p_hs, b_in0, p_cur, 1);
        gemm_tc(p_cur, nullptr, p_wth + OFF_WH0, p_wtl + OFF_WH0,
                nullptr, nullptr, nullptr, nullptr, p_hs, nullptr, 128, EPI_NONE, 2, 0);
        gather_kernel<<<GBK, 256>>>(p_hs, b_h0, p_cur2, 0);
        // fused u|r: u -> p_u, r*h_prev -> p_r
        gemm_tc(p_cur2, h0r, p_wth + OFF_WU0, p_wtl + OFF_WU0,
                bu0, br0, nullptr, h0r, p_u, p_r, 256, EPI_SIG, 4, 1);
        gemm_tc(p_cur2, p_r, p_wth + OFF_WC0, p_wtl + OFF_WC0,
                bc0, nullptr, p_u, h0r, h0w, nullptr, 256, EPI_GRU, 2, 0);

        // ---- layer 1 cell (input h0w, state h1r -> h1w) ----
        gemm_tc(h0w, nullptr, p_wth + OFF_WIN1, p_wtl + OFF_WIN1,
                nullptr, nullptr, nullptr, nullptr, p_hs, nullptr, 128, EPI_NONE, 2, 0);
        gather_kernel<<<GBK, 256>>>(p_hs, b_in1, p_cur, 1);
        gemm_tc(p_cur, nullptr, p_wth + OFF_WH1, p_wtl + OFF_WH1,
                nullptr, nullptr, nullptr, nullptr, p_hs, nullptr, 128, EPI_NONE, 2, 0);
        gather_kernel<<<GBK, 256>>>(p_hs, b_h1, p_cur2, 0);
        gemm_tc(p_cur2, h1r, p_wth + OFF_WU1, p_wtl + OFF_WU1,
                bu1, br1, nullptr, h1r, p_u, p_r, 256, EPI_SIG, 4, 1);
        gemm_tc(p_cur2, p_r, p_wth + OFF_WC1, p_wtl + OFF_WC1,
                bc1, nullptr, p_u, h1r, h1w, nullptr, 256, EPI_GRU, 2, 0);

        // ---- output projection ----
        gemm_tc(h1w, nullptr, p_wth + OFF_WOUT, p_wtl + OFF_WOUT,
                b_out, nullptr, nullptr, nullptr, out + (size_t)t * NN * HH, nullptr,
                128, EPI_BIAS, 2, 0);
    }
}

// round 15
// speedup vs baseline: 1.1997x; 1.1997x over previous
#include <cuda_runtime.h>
#include <cuda_fp16.h>
#include <math.h>
#include <stdint.h>

#define NN 50000
#define TT 8
#define HH 128
#define EE 800000
#define NBLK 49   // scan blocks of 1024

// ---------------- scratch (device globals; no allocation allowed) ----------
__device__ __align__(16) float g_h0a[NN * HH];
__device__ __align__(16) float g_h0b[NN * HH];
__device__ __align__(16) float g_h1a[NN * HH];
__device__ __align__(16) float g_h1b[NN * HH];
__device__ __align__(16) float g_hs[NN * HH];
__device__ __align__(16) float g_cur[NN * HH];
__device__ __align__(16) float g_cur2[NN * HH];
__device__ __align__(16) float g_u[NN * HH];
__device__ __align__(16) float g_r[NN * HH];     // holds r*h_prev (f32)
__device__ int   g_deg[NN];
__device__ int   g_rowptr[NN + 1];
__device__ int   g_cursor[NN];
__device__ int   g_csrc[EE];
__device__ float g_dinv[NN];
__device__ int   g_bsum[64];
__device__ int   g_boff[64];

// transposed + hi/lo-split weights (fp16), [N rows, K cols]
#define WT_TOTAL 278528
__device__ __align__(16) __half g_wt_hi[WT_TOTAL];
__device__ __align__(16) __half g_wt_lo[WT_TOTAL];

// WU/WR pairs contiguous: [Wu rows 0-127 | Wr rows 128-255], K=256
#define OFF_WIN0 0
#define OFF_WH0  16384
#define OFF_WU0  32768
#define OFF_WR0  65536
#define OFF_WC0  98304
#define OFF_WIN1 131072
#define OFF_WH1  147456
#define OFF_WU1  163840
#define OFF_WR1  196608
#define OFF_WC1  229376
#define OFF_WOUT 262144

// ---------------- warp-mma helpers (baseline PTX, no arch suffix) -----------
__device__ __forceinline__ uint32_t smem_u32(const void* p) {
    uint32_t a;
    asm("{ .reg .u64 t; cvta.to.shared.u64 t, %1; cvt.u32.u64 %0, t; }" : "=r"(a) : "l"(p));
    return a;
}
__device__ __forceinline__ void ldsm4(uint32_t& r0, uint32_t& r1, uint32_t& r2, uint32_t& r3,
                                      uint32_t addr) {
    asm volatile("ldmatrix.sync.aligned.m8n8.x4.shared.b16 {%0,%1,%2,%3}, [%4];"
                 : "=r"(r0), "=r"(r1), "=r"(r2), "=r"(r3) : "r"(addr));
}
__device__ __forceinline__ void mma_f16(float* d, const uint32_t* a, const uint32_t* b) {
    asm volatile(
        "mma.sync.aligned.m16n8k16.row.col.f32.f16.f16.f32 "
        "{%0,%1,%2,%3},{%4,%5,%6,%7},{%8,%9},{%0,%1,%2,%3};"
        : "+f"(d[0]), "+f"(d[1]), "+f"(d[2]), "+f"(d[3])
        : "r"(a[0]), "r"(a[1]), "r"(a[2]), "r"(a[3]), "r"(b[0]), "r"(b[1]));
}

// ---------------- small utility kernels ------------------------------------
__global__ void zero_f_kernel(float* p, int n) {
    for (int i = blockIdx.x * blockDim.x + threadIdx.x; i < n; i += gridDim.x * blockDim.x)
        p[i] = 0.0f;
}
__global__ void zero_deg_kernel(int n) {
    for (int i = blockIdx.x * blockDim.x + threadIdx.x; i < n; i += gridDim.x * blockDim.x)
        g_deg[i] = 0;
}
__global__ void hist_kernel(const int* __restrict__ dst, int e) {
    for (int i = blockIdx.x * blockDim.x + threadIdx.x; i < e; i += gridDim.x * blockDim.x)
        atomicAdd(&g_deg[dst[i]], 1);
}

// scan phase A: per-block exclusive scan of deg; partial rowptr + dinv + block sums
__global__ __launch_bounds__(1024) void scan_a_kernel(int n) {
    __shared__ int wsum[32];
    const int lane = threadIdx.x & 31;
    const int wid  = threadIdx.x >> 5;
    const int i = blockIdx.x * 1024 + threadIdx.x;
    int v = (i < n) ? g_deg[i] : 0;
    int incl = v;
    #pragma unroll
    for (int off = 1; off < 32; off <<= 1) {
        int t = __shfl_up_sync(0xffffffffu, incl, off);
        if (lane >= off) incl += t;
    }
    if (lane == 31) wsum[wid] = incl;
    __syncthreads();
    if (wid == 0) {
        int w = wsum[lane];
        #pragma unroll
        for (int off = 1; off < 32; off <<= 1) {
            int t = __shfl_up_sync(0xffffffffu, w, off);
            if (lane >= off) w += t;
        }
        wsum[lane] = w;
    }
    __syncthreads();
    int excl = (incl - v) + (wid > 0 ? wsum[wid - 1] : 0);
    if (i < n) {
        g_rowptr[i] = excl;
        g_dinv[i]   = rsqrtf((float)v + 1.0f);
    }
    if (threadIdx.x == 1023) g_bsum[blockIdx.x] = excl + v;
}

// scan phase B: exclusive scan of NBLK block sums (single block, 64 threads)
__global__ void scan_b_kernel(int n) {
    __shared__ int sh[64];
    const int tid = threadIdx.x;
    const int lane = tid & 31;
    const int w = tid >> 5;
    int v = (tid < NBLK) ? g_bsum[tid] : 0;
    int incl = v;
    #pragma unroll
    for (int off = 1; off < 32; off <<= 1) {
        int t = __shfl_up_sync(0xffffffffu, incl, off);
        if (lane >= off) incl += t;
    }
    if (lane == 31) sh[w] = incl;
    __syncthreads();
    int base = (w == 1) ? sh[0] : 0;
    incl += base;
    if (tid < NBLK) g_boff[tid] = incl - v;
    if (tid == NBLK - 1) g_rowptr[n] = incl;
}

// scan phase C: add block offsets, init cursor
__global__ __launch_bounds__(1024) void scan_c_kernel(int n) {
    const int i = blockIdx.x * 1024 + threadIdx.x;
    if (i < n) {
        int r = g_rowptr[i] + g_boff[blockIdx.x];
        g_rowptr[i] = r;
        g_cursor[i] = r;
    }
}

__global__ void fill_kernel(const int* __restrict__ src, const int* __restrict__ dst, int e) {
    for (int i = blockIdx.x * blockDim.x + threadIdx.x; i < e; i += gridDim.x * blockDim.x) {
        int slot = atomicAdd(&g_cursor[dst[i]], 1);
        g_csrc[slot] = src[i];
    }
}

// warp-per-node gather: lane handles 4 features (float4).
__global__ __launch_bounds__(256) void gather_kernel(
    const float* __restrict__ hs, const float* __restrict__ bias,
    float* __restrict__ out, int relu) {
    const int wid = threadIdx.x >> 5;
    const int lane = threadIdx.x & 31;
    const int node = blockIdx.x * 8 + wid;
    const int beg = g_rowptr[node];
    const int end = g_rowptr[node + 1];
    const float dn = g_dinv[node];
    const float4* hs4 = (const float4*)hs;
    const size_t fo = (size_t)node * 32 + lane;

    float4 a = hs4[fo];
    float4 acc = make_float4(dn * a.x, dn * a.y, dn * a.z, dn * a.w);
    int j = beg;
    for (; j + 4 <= end; j += 4) {
        int s0 = g_csrc[j], s1 = g_csrc[j + 1], s2 = g_csrc[j + 2], s3 = g_csrc[j + 3];
        float d0 = g_dinv[s0], d1 = g_dinv[s1], d2 = g_dinv[s2], d3 = g_dinv[s3];
        float4 v0 = hs4[(size_t)s0 * 32 + lane];
        float4 v1 = hs4[(size_t)s1 * 32 + lane];
        float4 v2 = hs4[(size_t)s2 * 32 + lane];
        float4 v3 = hs4[(size_t)s3 * 32 + lane];
        acc.x += d0 * v0.x + d1 * v1.x + d2 * v2.x + d3 * v3.x;
        acc.y += d0 * v0.y + d1 * v1.y + d2 * v2.y + d3 * v3.y;
        acc.z += d0 * v0.z + d1 * v1.z + d2 * v2.z + d3 * v3.z;
        acc.w += d0 * v0.w + d1 * v1.w + d2 * v2.w + d3 * v3.w;
    }
    for (; j < end; ++j) {
        int s = g_csrc[j];
        float d = g_dinv[s];
        float4 v = hs4[(size_t)s * 32 + lane];
        acc.x += d * v.x; acc.y += d * v.y; acc.z += d * v.z; acc.w += d * v.w;
    }
    float4 b = ((const float4*)bias)[lane];
    float4 r;
    r.x = dn * acc.x + b.x;
    r.y = dn * acc.y + b.y;
    r.z = dn * acc.z + b.z;
    r.w = dn * acc.w + b.w;
    if (relu) {
        r.x = fmaxf(r.x, 0.0f); r.y = fmaxf(r.y, 0.0f);
        r.z = fmaxf(r.z, 0.0f); r.w = fmaxf(r.w, 0.0f);
    }
    ((float4*)out)[fo] = r;
}

// weight prep: src [K,128] f32 row-major -> dst [128,K] fp16 hi/lo (transposed)
__global__ void prep_w_kernel(const float* __restrict__ W,
                              __half* __restrict__ hi,
                              __half* __restrict__ lo, int K) {
    int total = K * 128;
    for (int idx = blockIdx.x * blockDim.x + threadIdx.x; idx < total;
         idx += gridDim.x * blockDim.x) {
        int k = idx >> 7;
        int nn = idx & 127;
        float v = W[idx];
        __half h = __float2half_rn(v);
        __half l = __float2half_rn(v - __half2float(h));
        hi[(size_t)nn * K + k] = h;
        lo[(size_t)nn * K + k] = l;
    }
}

// ---------------- tensor-core GEMM via mma.sync (2-pass fp16) ---------------
// D = A_f16 @ (W_hi + W_lo): activations single fp16, weights split 22-bit.
// Block tile 128(M) x 64(N), 8 warps of 32x32, 2 CTAs/SM.
#define EPI_NONE 0
#define EPI_SIG  1
#define EPI_GRU  2
#define EPI_BIAS 3

#define ROWB 80
#define SM_A   0
#define SM_BHI (128 * ROWB)               // 10240
#define SM_BLO (128 * ROWB + 64 * ROWB)   // 15360
#define SM_TOT (128 * ROWB + 2 * 64 * ROWB)  // 20480

__global__ __launch_bounds__(256, 2) void gemm_mma_kernel(
    const float* __restrict__ A1, const float* __restrict__ A2,
    const __half* __restrict__ Bt_hi, const __half* __restrict__ Bt_lo,
    const float* __restrict__ bias, const float* __restrict__ bias2,
    const float* __restrict__ u, const float* __restrict__ hprev,
    float* __restrict__ out, float* __restrict__ out2,
    int n, int K, int epi, int split)
{
    extern __shared__ __align__(16) char smem[];
    const uint32_t sb = smem_u32(smem);
    const int tid = threadIdx.x;
    const int wid = tid >> 5;
    const int lane = tid & 31;
    const int row0 = blockIdx.x * 128;
    const int n0 = blockIdx.y * 64;
    const int wm = wid & 3;
    const int wn = wid >> 2;

    const int ar[4] = { (tid + 0) >> 3, (tid + 256) >> 3, (tid + 512) >> 3, (tid + 768) >> 3 };
    const int ac4 = (tid & 7) * 4;
    const int br_ = tid >> 2;
    const int bc8 = (tid & 3) * 8;

    float acc[2][4][4];
    #pragma unroll
    for (int i = 0; i < 2; i++)
        #pragma unroll
        for (int j = 0; j < 4; j++)
            #pragma unroll
            for (int q = 0; q < 4; q++) acc[i][j][q] = 0.0f;

    const int nc = K >> 5;
    float4 pa[4];
    uint4 pbh, pbl;

    {
        #pragma unroll
        for (int it = 0; it < 4; it++) {
            int grow = row0 + ar[it];
            pa[it] = (grow < n) ? *(const float4*)(A1 + (size_t)grow * 128 + ac4)
                                : make_float4(0.f, 0.f, 0.f, 0.f);
        }
        size_t goff = (size_t)(n0 + br_) * K + bc8;
        pbh = *(const uint4*)(Bt_hi + goff);
        pbl = *(const uint4*)(Bt_lo + goff);
    }

    for (int c = 0; c < nc; c++) {
        // convert/store A chunk (single fp16)
        #pragma unroll
        for (int it = 0; it < 4; it++) {
            float4 v = pa[it];
            __half h0 = __float2half_rn(v.x);
            __half h1 = __float2half_rn(v.y);
            __half h2 = __float2half_rn(v.z);
            __half h3 = __float2half_rn(v.w);
            uint32_t hA = (uint32_t)__half_as_ushort(h0) |
                          ((uint32_t)__half_as_ushort(h1) << 16);
            uint32_t hB = (uint32_t)__half_as_ushort(h2) |
                          ((uint32_t)__half_as_ushort(h3) << 16);
            uint32_t off = ar[it] * ROWB + ac4 * 2;
            *(uint2*)(smem + SM_A + off) = make_uint2(hA, hB);
        }
        {
            uint32_t off = br_ * ROWB + bc8 * 2;
            *(uint4*)(smem + SM_BHI + off) = pbh;
            *(uint4*)(smem + SM_BLO + off) = pbl;
        }
        __syncthreads();

        if (c + 1 < nc) {
            const int kn = (c + 1) * 32;
            const float* Asrc = (kn >= 128) ? A2 : A1;
            const int kln = (kn >= 128) ? kn - 128 : kn;
            #pragma unroll
            for (int it = 0; it < 4; it++) {
                int grow = row0 + ar[it];
                pa[it] = (grow < n) ? *(const float4*)(Asrc + (size_t)grow * 128 + kln + ac4)
                                    : make_float4(0.f, 0.f, 0.f, 0.f);
            }
            size_t goff = (size_t)(n0 + br_) * K + kn + bc8;
            pbh = *(const uint4*)(Bt_hi + goff);
            pbl = *(const uint4*)(Bt_lo + goff);
        }

        #pragma unroll
        for (int ks = 0; ks < 2; ks++) {
            uint32_t ah[2][4];
            #pragma unroll
            for (int mt = 0; mt < 2; mt++) {
                uint32_t addr = sb + SM_A +
                    (uint32_t)(wm * 32 + mt * 16 + (lane & 15)) * ROWB +
                    ks * 32 + (lane >> 4) * 16;
                ldsm4(ah[mt][0], ah[mt][1], ah[mt][2], ah[mt][3], addr);
            }
            uint32_t bh0[4], bh1[4], bl0[4], bl1[4];
            {
                uint32_t baddr = sb + SM_BHI + (uint32_t)(wn * 32 + lane) * ROWB + ks * 32;
                ldsm4(bh0[0], bh0[1], bh0[2], bh0[3], baddr);
                ldsm4(bh1[0], bh1[1], bh1[2], bh1[3], baddr + 16);
                ldsm4(bl0[0], bl0[1], bl0[2], bl0[3], baddr + (SM_BLO - SM_BHI));
                ldsm4(bl1[0], bl1[1], bl1[2], bl1[3], baddr + (SM_BLO - SM_BHI) + 16);
            }
            #pragma unroll
            for (int mt = 0; mt < 2; mt++) {
                #pragma unroll
                for (int nt = 0; nt < 4; nt++) {
                    uint32_t bh[2] = {bh0[nt], bh1[nt]};
                    uint32_t bl[2] = {bl0[nt], bl1[nt]};
                    mma_f16(acc[mt][nt], ah[mt], bh);
                    mma_f16(acc[mt][nt], ah[mt], bl);
                }
            }
        }
        __syncthreads();
    }

    // ---- epilogue ----
    const int urpart = split ? (int)(blockIdx.y >> 1) : 0;
    const float* biasX = (split && urpart) ? bias2 : bias;
    float* outX = (split && urpart) ? out2 : out;
    const int ybase = (blockIdx.y & 1) * 64;
    const int qrow = lane >> 2;
    const int qcol = (lane & 3) * 2;
    const int gc_base = ybase + wn * 32;
    #pragma unroll
    for (int mt = 0; mt < 2; mt++) {
        #pragma unroll
        for (int rs = 0; rs < 2; rs++) {
            int grow = row0 + wm * 32 + mt * 16 + rs * 8 + qrow;
            if (grow >= n) continue;
            size_t rbase = (size_t)grow * 128;
            #pragma unroll
            for (int nt = 0; nt < 4; nt++) {
                int gc = gc_base + nt * 8 + qcol;
                float v0 = acc[mt][nt][rs * 2];
                float v1 = acc[mt][nt][rs * 2 + 1];
                float r0, r1;
                if (epi == EPI_NONE) {
                    r0 = v0; r1 = v1;
                } else if (epi == EPI_SIG) {
                    r0 = 1.0f / (1.0f + expf(-(v0 + biasX[gc])));
                    r1 = 1.0f / (1.0f + expf(-(v1 + biasX[gc + 1])));
                    // r-half of fused u|r: write r*h_prev -> consumed as plain A2
                    if (urpart && hprev) {
                        r0 *= hprev[rbase + gc];
                        r1 *= hprev[rbase + gc + 1];
                    }
                } else if (epi == EPI_GRU) {
                    float a0 = tanhf(v0 + biasX[gc]);
                    float a1 = tanhf(v1 + biasX[gc + 1]);
                    float hp0 = hprev[rbase + gc], hp1 = hprev[rbase + gc + 1];
                    float u0 = u[rbase + gc], u1 = u[rbase + gc + 1];
                    r0 = hp0 + u0 * (a0 - hp0);
                    r1 = hp1 + u1 * (a1 - hp1);
                } else {
                    r0 = v0 + biasX[gc]; r1 = v1 + biasX[gc + 1];
                }
                *(float2*)(outX + rbase + gc) = make_float2(r0, r1);
            }
        }
    }
}

// ---------------- driver ------------------------------------------------------
static inline void gemm_tc(const float* A1, const float* A2,
                           const __half* bh, const __half* bl,
                           const float* bias, const float* bias2,
                           const float* u, const float* hprev,
                           float* out, float* out2, int K, int epi, int ny, int split) {
    dim3 grid((NN + 127) / 128, ny);
    gemm_mma_kernel<<<grid, 256, SM_TOT>>>(A1, A2, bh, bl, bias, bias2,
                                           u, hprev, out, out2, NN, K, epi, split);
}

extern "C" void kernel_launch(void* const* d_in, const int* in_sizes, int n_in,
                              void* d_out, int out_size) {
    const float* x_seq = (const float*)d_in[0];
    const int*   ei    = (const int*)d_in[1];
    const float* W_in0 = (const float*)d_in[2];
    const float* b_in0 = (const float*)d_in[3];
    const float* W_h0  = (const float*)d_in[4];
    const float* b_h0  = (const float*)d_in[5];
    const float* Wu0   = (const float*)d_in[6];
    const float* bu0   = (const float*)d_in[7];
    const float* Wr0   = (const float*)d_in[8];
    const float* br0   = (const float*)d_in[9];
    const float* Wc0   = (const float*)d_in[10];
    const float* bc0   = (const float*)d_in[11];
    const float* W_in1 = (const float*)d_in[12];
    const float* b_in1 = (const float*)d_in[13];
    const float* W_h1  = (const float*)d_in[14];
    const float* b_h1  = (const float*)d_in[15];
    const float* Wu1   = (const float*)d_in[16];
    const float* bu1   = (const float*)d_in[17];
    const float* Wr1   = (const float*)d_in[18];
    const float* br1   = (const float*)d_in[19];
    const float* Wc1   = (const float*)d_in[20];
    const float* bc1   = (const float*)d_in[21];
    const float* W_out = (const float*)d_in[22];
    const float* b_out = (const float*)d_in[23];
    float* out = (float*)d_out;

    float *p_h0a, *p_h0b, *p_h1a, *p_h1b;
    float *p_hs, *p_cur, *p_cur2, *p_u, *p_r;
    __half *p_wth, *p_wtl;
    cudaGetSymbolAddress((void**)&p_h0a,  g_h0a);
    cudaGetSymbolAddress((void**)&p_h0b,  g_h0b);
    cudaGetSymbolAddress((void**)&p_h1a,  g_h1a);
    cudaGetSymbolAddress((void**)&p_h1b,  g_h1b);
    cudaGetSymbolAddress((void**)&p_hs,   g_hs);
    cudaGetSymbolAddress((void**)&p_cur,  g_cur);
    cudaGetSymbolAddress((void**)&p_cur2, g_cur2);
    cudaGetSymbolAddress((void**)&p_u,    g_u);
    cudaGetSymbolAddress((void**)&p_r,    g_r);
    cudaGetSymbolAddress((void**)&p_wth,  g_wt_hi);
    cudaGetSymbolAddress((void**)&p_wtl,  g_wt_lo);

    const int EB = (EE + 255) / 256;
    const int PB = 128;
    const int GBK = NN / 8;   // gather blocks (8 nodes/block)

    for (int t = 0; t < TT; t++) {
        float* h0r = (t & 1) ? p_h0b : p_h0a;
        float* h0w = (t & 1) ? p_h0a : p_h0b;
        float* h1r = (t & 1) ? p_h1b : p_h1a;
        float* h1w = (t & 1) ? p_h1a : p_h1b;

        const int* src = ei + (size_t)t * 2 * EE;
        const int* dst = src + EE;
        const float* xin = x_seq + (size_t)t * NN * HH;

        // t=0 launch order: zero_deg(0), hist(1), prep(2), gemm(3) <- ncu idx 3
        zero_deg_kernel<<<128, 256>>>(NN);
        hist_kernel<<<EB, 256>>>(dst, EE);
        if (t == 0)
            prep_w_kernel<<<PB, 256>>>(W_in0, p_wth + OFF_WIN0, p_wtl + OFF_WIN0, 128);
        gemm_tc(xin, nullptr, p_wth + OFF_WIN0, p_wtl + OFF_WIN0,
                nullptr, nullptr, nullptr, nullptr, p_hs, nullptr, 128, EPI_NONE, 2, 0);
        scan_a_kernel<<<NBLK, 1024>>>(NN);
        scan_b_kernel<<<1, 64>>>(NN);
        scan_c_kernel<<<NBLK, 1024>>>(NN);
        fill_kernel<<<EB, 256>>>(src, dst, EE);
        if (t == 0) {
            zero_f_kernel<<<512, 256>>>(p_h0a, NN * HH);
            zero_f_kernel<<<512, 256>>>(p_h1a, NN * HH);
            prep_w_kernel<<<PB, 256>>>(W_h0,  p_wth + OFF_WH0,  p_wtl + OFF_WH0,  128);
            prep_w_kernel<<<PB, 256>>>(Wu0,   p_wth + OFF_WU0,  p_wtl + OFF_WU0,  256);
            prep_w_kernel<<<PB, 256>>>(Wr0,   p_wth + OFF_WR0,  p_wtl + OFF_WR0,  256);
            prep_w_kernel<<<PB, 256>>>(Wc0,   p_wth + OFF_WC0,  p_wtl + OFF_WC0,  256);
            prep_w_kernel<<<PB, 256>>>(W_in1, p_wth + OFF_WIN1, p_wtl + OFF_WIN1, 128);
            prep_w_kernel<<<PB, 256>>>(W_h1,  p_wth + OFF_WH1,  p_wtl + OFF_WH1,  128);
            prep_w_kernel<<<PB, 256>>>(Wu1,   p_wth + OFF_WU1,  p_wtl + OFF_WU1,  256);
            prep_w_kernel<<<PB, 256>>>(Wr1,   p_wth + OFF_WR1,  p_wtl + OFF_WR1,  256);
            prep_w_kernel<<<PB, 256>>>(Wc1,   p_wth + OFF_WC1,  p_wtl + OFF_WC1,  256);
            prep_w_kernel<<<PB, 256>>>(W_out, p_wth + OFF_WOUT, p_wtl + OFF_WOUT, 128);
        }

        // ---- layer 0 cell (state h0r -> h0w) ----
        gather_kernel<<<GBK, 256>>>(p_hs, b_in0, p_cur, 1);
        gemm_tc(p_cur, nullptr, p_wth + OFF_WH0, p_wtl + OFF_WH0,
                nullptr, nullptr, nullptr, nullptr, p_hs, nullptr, 128, EPI_NONE, 2, 0);
        gather_kernel<<<GBK, 256>>>(p_hs, b_h0, p_cur2, 0);
        // fused u|r: u -> p_u, r*h_prev -> p_r
        gemm_tc(p_cur2, h0r, p_wth + OFF_WU0, p_wtl + OFF_WU0,
                bu0, br0, nullptr, h0r, p_u, p_r, 256, EPI_SIG, 4, 1);
        gemm_tc(p_cur2, p_r, p_wth + OFF_WC0, p_wtl + OFF_WC0,
                bc0, nullptr, p_u, h0r, h0w, nullptr, 256, EPI_GRU, 2, 0);

        // ---- layer 1 cell (input h0w, state h1r -> h1w) ----
        gemm_tc(h0w, nullptr, p_wth + OFF_WIN1, p_wtl + OFF_WIN1,
                nullptr, nullptr, nullptr, nullptr, p_hs, nullptr, 128, EPI_NONE, 2, 0);
        gather_kernel<<<GBK, 256>>>(p_hs, b_in1, p_cur, 1);
        gemm_tc(p_cur, nullptr, p_wth + OFF_WH1, p_wtl + OFF_WH1,
                nullptr, nullptr, nullptr, nullptr, p_hs, nullptr, 128, EPI_NONE, 2, 0);
        gather_kernel<<<GBK, 256>>>(p_hs, b_h1, p_cur2, 0);
        gemm_tc(p_cur2, h1r, p_wth + OFF_WU1, p_wtl + OFF_WU1,
                bu1, br1, nullptr, h1r, p_u, p_r, 256, EPI_SIG, 4, 1);
        gemm_tc(p_cur2, p_r, p_wth + OFF_WC1, p_wtl + OFF_WC1,
                bc1, nullptr, p_u, h1r, h1w, nullptr, 256, EPI_GRU, 2, 0);

        // ---- output projection ----
        gemm_tc(h1w, nullptr, p_wth + OFF_WOUT, p_wtl + OFF_WOUT,
                b_out, nullptr, nullptr, nullptr, out + (size_t)t * NN * HH, nullptr,
                128, EPI_BIAS, 2, 0);
    }
}

// round 16
// speedup vs baseline: 1.3190x; 1.0994x over previous
#include <cuda_runtime.h>
#include <cuda_fp16.h>
#include <math.h>
#include <stdint.h>

#define NN 50000
#define TT 8
#define HH 128
#define EE 800000
#define NBLK 49   // scan blocks of 1024

// ---------------- scratch (device globals; no allocation allowed) ----------
__device__ __align__(16) float g_h0a[NN * HH];
__device__ __align__(16) float g_h0b[NN * HH];
__device__ __align__(16) float g_h1a[NN * HH];
__device__ __align__(16) float g_h1b[NN * HH];
__device__ __align__(16) float g_hs[NN * HH];
__device__ __align__(16) float g_cur[NN * HH];
__device__ __align__(16) float g_cur2[NN * HH];
__device__ __align__(16) float g_u[NN * HH];
__device__ __align__(16) float g_r[NN * HH];     // holds r*h_prev (f32)
__device__ int   g_deg[NN];
__device__ int   g_rowptr[NN + 1];
__device__ int   g_cursor[NN];
__device__ int   g_csrc[EE];
__device__ float g_dinv[NN];
__device__ int   g_bsum[64];
__device__ int   g_boff[64];

// transposed fp16 weights, [N rows, K cols]
#define WT_TOTAL 278528
__device__ __align__(16) __half g_wt[WT_TOTAL];

// WU/WR pairs contiguous: [Wu rows 0-127 | Wr rows 128-255], K=256
#define OFF_WIN0 0
#define OFF_WH0  16384
#define OFF_WU0  32768
#define OFF_WR0  65536
#define OFF_WC0  98304
#define OFF_WIN1 131072
#define OFF_WH1  147456
#define OFF_WU1  163840
#define OFF_WR1  196608
#define OFF_WC1  229376
#define OFF_WOUT 262144

// ---------------- warp-mma helpers (baseline PTX, no arch suffix) -----------
__device__ __forceinline__ uint32_t smem_u32(const void* p) {
    uint32_t a;
    asm("{ .reg .u64 t; cvta.to.shared.u64 t, %1; cvt.u32.u64 %0, t; }" : "=r"(a) : "l"(p));
    return a;
}
__device__ __forceinline__ void ldsm4(uint32_t& r0, uint32_t& r1, uint32_t& r2, uint32_t& r3,
                                      uint32_t addr) {
    asm volatile("ldmatrix.sync.aligned.m8n8.x4.shared.b16 {%0,%1,%2,%3}, [%4];"
                 : "=r"(r0), "=r"(r1), "=r"(r2), "=r"(r3) : "r"(addr));
}
__device__ __forceinline__ void mma_f16(float* d, const uint32_t* a, const uint32_t* b) {
    asm volatile(
        "mma.sync.aligned.m16n8k16.row.col.f32.f16.f16.f32 "
        "{%0,%1,%2,%3},{%4,%5,%6,%7},{%8,%9},{%0,%1,%2,%3};"
        : "+f"(d[0]), "+f"(d[1]), "+f"(d[2]), "+f"(d[3])
        : "r"(a[0]), "r"(a[1]), "r"(a[2]), "r"(a[3]), "r"(b[0]), "r"(b[1]));
}

// ---------------- small utility kernels ------------------------------------
__global__ void zero_f_kernel(float* p, int n) {
    for (int i = blockIdx.x * blockDim.x + threadIdx.x; i < n; i += gridDim.x * blockDim.x)
        p[i] = 0.0f;
}
__global__ void zero_deg_kernel(int n) {
    for (int i = blockIdx.x * blockDim.x + threadIdx.x; i < n; i += gridDim.x * blockDim.x)
        g_deg[i] = 0;
}
__global__ void hist_kernel(const int* __restrict__ dst, int e) {
    for (int i = blockIdx.x * blockDim.x + threadIdx.x; i < e; i += gridDim.x * blockDim.x)
        atomicAdd(&g_deg[dst[i]], 1);
}

// scan phase A: per-block exclusive scan of deg; partial rowptr + dinv + block sums
__global__ __launch_bounds__(1024) void scan_a_kernel(int n) {
    __shared__ int wsum[32];
    const int lane = threadIdx.x & 31;
    const int wid  = threadIdx.x >> 5;
    const int i = blockIdx.x * 1024 + threadIdx.x;
    int v = (i < n) ? g_deg[i] : 0;
    int incl = v;
    #pragma unroll
    for (int off = 1; off < 32; off <<= 1) {
        int t = __shfl_up_sync(0xffffffffu, incl, off);
        if (lane >= off) incl += t;
    }
    if (lane == 31) wsum[wid] = incl;
    __syncthreads();
    if (wid == 0) {
        int w = wsum[lane];
        #pragma unroll
        for (int off = 1; off < 32; off <<= 1) {
            int t = __shfl_up_sync(0xffffffffu, w, off);
            if (lane >= off) w += t;
        }
        wsum[lane] = w;
    }
    __syncthreads();
    int excl = (incl - v) + (wid > 0 ? wsum[wid - 1] : 0);
    if (i < n) {
        g_rowptr[i] = excl;
        g_dinv[i]   = rsqrtf((float)v + 1.0f);
    }
    if (threadIdx.x == 1023) g_bsum[blockIdx.x] = excl + v;
}

// scan phase B: exclusive scan of NBLK block sums (single block, 64 threads)
__global__ void scan_b_kernel(int n) {
    __shared__ int sh[64];
    const int tid = threadIdx.x;
    const int lane = tid & 31;
    const int w = tid >> 5;
    int v = (tid < NBLK) ? g_bsum[tid] : 0;
    int incl = v;
    #pragma unroll
    for (int off = 1; off < 32; off <<= 1) {
        int t = __shfl_up_sync(0xffffffffu, incl, off);
        if (lane >= off) incl += t;
    }
    if (lane == 31) sh[w] = incl;
    __syncthreads();
    int base = (w == 1) ? sh[0] : 0;
    incl += base;
    if (tid < NBLK) g_boff[tid] = incl - v;
    if (tid == NBLK - 1) g_rowptr[n] = incl;
}

// scan phase C: add block offsets, init cursor
__global__ __launch_bounds__(1024) void scan_c_kernel(int n) {
    const int i = blockIdx.x * 1024 + threadIdx.x;
    if (i < n) {
        int r = g_rowptr[i] + g_boff[blockIdx.x];
        g_rowptr[i] = r;
        g_cursor[i] = r;
    }
}

__global__ void fill_kernel(const int* __restrict__ src, const int* __restrict__ dst, int e) {
    for (int i = blockIdx.x * blockDim.x + threadIdx.x; i < e; i += gridDim.x * blockDim.x) {
        int slot = atomicAdd(&g_cursor[dst[i]], 1);
        g_csrc[slot] = src[i];
    }
}

// warp-per-node gather: lane handles 4 features (float4).
__global__ __launch_bounds__(256) void gather_kernel(
    const float* __restrict__ hs, const float* __restrict__ bias,
    float* __restrict__ out, int relu) {
    const int wid = threadIdx.x >> 5;
    const int lane = threadIdx.x & 31;
    const int node = blockIdx.x * 8 + wid;
    const int beg = g_rowptr[node];
    const int end = g_rowptr[node + 1];
    const float dn = g_dinv[node];
    const float4* hs4 = (const float4*)hs;
    const size_t fo = (size_t)node * 32 + lane;

    float4 a = hs4[fo];
    float4 acc = make_float4(dn * a.x, dn * a.y, dn * a.z, dn * a.w);
    int j = beg;
    for (; j + 4 <= end; j += 4) {
        int s0 = g_csrc[j], s1 = g_csrc[j + 1], s2 = g_csrc[j + 2], s3 = g_csrc[j + 3];
        float d0 = g_dinv[s0], d1 = g_dinv[s1], d2 = g_dinv[s2], d3 = g_dinv[s3];
        float4 v0 = hs4[(size_t)s0 * 32 + lane];
        float4 v1 = hs4[(size_t)s1 * 32 + lane];
        float4 v2 = hs4[(size_t)s2 * 32 + lane];
        float4 v3 = hs4[(size_t)s3 * 32 + lane];
        acc.x += d0 * v0.x + d1 * v1.x + d2 * v2.x + d3 * v3.x;
        acc.y += d0 * v0.y + d1 * v1.y + d2 * v2.y + d3 * v3.y;
        acc.z += d0 * v0.z + d1 * v1.z + d2 * v2.z + d3 * v3.z;
        acc.w += d0 * v0.w + d1 * v1.w + d2 * v2.w + d3 * v3.w;
    }
    for (; j < end; ++j) {
        int s = g_csrc[j];
        float d = g_dinv[s];
        float4 v = hs4[(size_t)s * 32 + lane];
        acc.x += d * v.x; acc.y += d * v.y; acc.z += d * v.z; acc.w += d * v.w;
    }
    float4 b = ((const float4*)bias)[lane];
    float4 r;
    r.x = dn * acc.x + b.x;
    r.y = dn * acc.y + b.y;
    r.z = dn * acc.z + b.z;
    r.w = dn * acc.w + b.w;
    if (relu) {
        r.x = fmaxf(r.x, 0.0f); r.y = fmaxf(r.y, 0.0f);
        r.z = fmaxf(r.z, 0.0f); r.w = fmaxf(r.w, 0.0f);
    }
    ((float4*)out)[fo] = r;
}

// weight prep: src [K,128] f32 row-major -> dst [128,K] fp16 (transposed)
__global__ void prep_w_kernel(const float* __restrict__ W,
                              __half* __restrict__ hi, int K) {
    int total = K * 128;
    for (int idx = blockIdx.x * blockDim.x + threadIdx.x; idx < total;
         idx += gridDim.x * blockDim.x) {
        int k = idx >> 7;
        int nn = idx & 127;
        hi[(size_t)nn * K + k] = __float2half_rn(W[idx]);
    }
}

// ---------------- tensor-core GEMM via mma.sync (single-pass fp16) ----------
// Block tile 128(M) x 64(N), 8 warps of 32x32, 2 CTAs/SM.
#define EPI_NONE 0
#define EPI_SIG  1
#define EPI_GRU  2
#define EPI_BIAS 3

#define ROWB 80
#define SM_A   0
#define SM_B   (128 * ROWB)               // 10240
#define SM_TOT (128 * ROWB + 64 * ROWB)   // 15360

__global__ __launch_bounds__(256, 2) void gemm_mma_kernel(
    const float* __restrict__ A1, const float* __restrict__ A2,
    const __half* __restrict__ Bt,
    const float* __restrict__ bias, const float* __restrict__ bias2,
    const float* __restrict__ u, const float* __restrict__ hprev,
    float* __restrict__ out, float* __restrict__ out2,
    int n, int K, int epi, int split)
{
    extern __shared__ __align__(16) char smem[];
    const uint32_t sb = smem_u32(smem);
    const int tid = threadIdx.x;
    const int wid = tid >> 5;
    const int lane = tid & 31;
    const int row0 = blockIdx.x * 128;
    const int n0 = blockIdx.y * 64;
    const int wm = wid & 3;
    const int wn = wid >> 2;

    const int ar[4] = { (tid + 0) >> 3, (tid + 256) >> 3, (tid + 512) >> 3, (tid + 768) >> 3 };
    const int ac4 = (tid & 7) * 4;
    const int br_ = tid >> 2;
    const int bc8 = (tid & 3) * 8;

    float acc[2][4][4];
    #pragma unroll
    for (int i = 0; i < 2; i++)
        #pragma unroll
        for (int j = 0; j < 4; j++)
            #pragma unroll
            for (int q = 0; q < 4; q++) acc[i][j][q] = 0.0f;

    const int nc = K >> 5;
    float4 pa[4];
    uint4 pb;

    {
        #pragma unroll
        for (int it = 0; it < 4; it++) {
            int grow = row0 + ar[it];
            pa[it] = (grow < n) ? *(const float4*)(A1 + (size_t)grow * 128 + ac4)
                                : make_float4(0.f, 0.f, 0.f, 0.f);
        }
        size_t goff = (size_t)(n0 + br_) * K + bc8;
        pb = *(const uint4*)(Bt + goff);
    }

    for (int c = 0; c < nc; c++) {
        // convert/store A chunk (single fp16)
        #pragma unroll
        for (int it = 0; it < 4; it++) {
            float4 v = pa[it];
            __half h0 = __float2half_rn(v.x);
            __half h1 = __float2half_rn(v.y);
            __half h2 = __float2half_rn(v.z);
            __half h3 = __float2half_rn(v.w);
            uint32_t hA = (uint32_t)__half_as_ushort(h0) |
                          ((uint32_t)__half_as_ushort(h1) << 16);
            uint32_t hB = (uint32_t)__half_as_ushort(h2) |
                          ((uint32_t)__half_as_ushort(h3) << 16);
            uint32_t off = ar[it] * ROWB + ac4 * 2;
            *(uint2*)(smem + SM_A + off) = make_uint2(hA, hB);
        }
        {
            uint32_t off = br_ * ROWB + bc8 * 2;
            *(uint4*)(smem + SM_B + off) = pb;
        }
        __syncthreads();

        if (c + 1 < nc) {
            const int kn = (c + 1) * 32;
            const float* Asrc = (kn >= 128) ? A2 : A1;
            const int kln = (kn >= 128) ? kn - 128 : kn;
            #pragma unroll
            for (int it = 0; it < 4; it++) {
                int grow = row0 + ar[it];
                pa[it] = (grow < n) ? *(const float4*)(Asrc + (size_t)grow * 128 + kln + ac4)
                                    : make_float4(0.f, 0.f, 0.f, 0.f);
            }
            size_t goff = (size_t)(n0 + br_) * K + kn + bc8;
            pb = *(const uint4*)(Bt + goff);
        }

        #pragma unroll
        for (int ks = 0; ks < 2; ks++) {
            uint32_t ah[2][4];
            #pragma unroll
            for (int mt = 0; mt < 2; mt++) {
                uint32_t addr = sb + SM_A +
                    (uint32_t)(wm * 32 + mt * 16 + (lane & 15)) * ROWB +
                    ks * 32 + (lane >> 4) * 16;
                ldsm4(ah[mt][0], ah[mt][1], ah[mt][2], ah[mt][3], addr);
            }
            uint32_t bh0[4], bh1[4];
            {
                uint32_t baddr = sb + SM_B + (uint32_t)(wn * 32 + lane) * ROWB + ks * 32;
                ldsm4(bh0[0], bh0[1], bh0[2], bh0[3], baddr);
                ldsm4(bh1[0], bh1[1], bh1[2], bh1[3], baddr + 16);
            }
            #pragma unroll
            for (int mt = 0; mt < 2; mt++) {
                #pragma unroll
                for (int nt = 0; nt < 4; nt++) {
                    uint32_t bh[2] = {bh0[nt], bh1[nt]};
                    mma_f16(acc[mt][nt], ah[mt], bh);
                }
            }
        }
        __syncthreads();
    }

    // ---- epilogue ----
    const int urpart = split ? (int)(blockIdx.y >> 1) : 0;
    const float* biasX = (split && urpart) ? bias2 : bias;
    float* outX = (split && urpart) ? out2 : out;
    const int ybase = (blockIdx.y & 1) * 64;
    const int qrow = lane >> 2;
    const int qcol = (lane & 3) * 2;
    const int gc_base = ybase + wn * 32;
    #pragma unroll
    for (int mt = 0; mt < 2; mt++) {
        #pragma unroll
        for (int rs = 0; rs < 2; rs++) {
            int grow = row0 + wm * 32 + mt * 16 + rs * 8 + qrow;
            if (grow >= n) continue;
            size_t rbase = (size_t)grow * 128;
            #pragma unroll
            for (int nt = 0; nt < 4; nt++) {
                int gc = gc_base + nt * 8 + qcol;
                float v0 = acc[mt][nt][rs * 2];
                float v1 = acc[mt][nt][rs * 2 + 1];
                float r0, r1;
                if (epi == EPI_NONE) {
                    r0 = v0; r1 = v1;
                } else if (epi == EPI_SIG) {
                    r0 = 1.0f / (1.0f + expf(-(v0 + biasX[gc])));
                    r1 = 1.0f / (1.0f + expf(-(v1 + biasX[gc + 1])));
                    // r-half of fused u|r: write r*h_prev -> consumed as plain A2
                    if (urpart && hprev) {
                        r0 *= hprev[rbase + gc];
                        r1 *= hprev[rbase + gc + 1];
                    }
                } else if (epi == EPI_GRU) {
                    float a0 = tanhf(v0 + biasX[gc]);
                    float a1 = tanhf(v1 + biasX[gc + 1]);
                    float hp0 = hprev[rbase + gc], hp1 = hprev[rbase + gc + 1];
                    float u0 = u[rbase + gc], u1 = u[rbase + gc + 1];
                    r0 = hp0 + u0 * (a0 - hp0);
                    r1 = hp1 + u1 * (a1 - hp1);
                } else {
                    r0 = v0 + biasX[gc]; r1 = v1 + biasX[gc + 1];
                }
                *(float2*)(outX + rbase + gc) = make_float2(r0, r1);
            }
        }
    }
}

// ---------------- driver ------------------------------------------------------
static inline void gemm_tc(const float* A1, const float* A2, const __half* bt,
                           const float* bias, const float* bias2,
                           const float* u, const float* hprev,
                           float* out, float* out2, int K, int epi, int ny, int split) {
    dim3 grid((NN + 127) / 128, ny);
    gemm_mma_kernel<<<grid, 256, SM_TOT>>>(A1, A2, bt, bias, bias2,
                                           u, hprev, out, out2, NN, K, epi, split);
}

extern "C" void kernel_launch(void* const* d_in, const int* in_sizes, int n_in,
                              void* d_out, int out_size) {
    const float* x_seq = (const float*)d_in[0];
    const int*   ei    = (const int*)d_in[1];
    const float* W_in0 = (const float*)d_in[2];
    const float* b_in0 = (const float*)d_in[3];
    const float* W_h0  = (const float*)d_in[4];
    const float* b_h0  = (const float*)d_in[5];
    const float* Wu0   = (const float*)d_in[6];
    const float* bu0   = (const float*)d_in[7];
    const float* Wr0   = (const float*)d_in[8];
    const float* br0   = (const float*)d_in[9];
    const float* Wc0   = (const float*)d_in[10];
    const float* bc0   = (const float*)d_in[11];
    const float* W_in1 = (const float*)d_in[12];
    const float* b_in1 = (const float*)d_in[13];
    const float* W_h1  = (const float*)d_in[14];
    const float* b_h1  = (const float*)d_in[15];
    const float* Wu1   = (const float*)d_in[16];
    const float* bu1   = (const float*)d_in[17];
    const float* Wr1   = (const float*)d_in[18];
    const float* br1   = (const float*)d_in[19];
    const float* Wc1   = (const float*)d_in[20];
    const float* bc1   = (const float*)d_in[21];
    const float* W_out = (const float*)d_in[22];
    const float* b_out = (const float*)d_in[23];
    float* out = (float*)d_out;

    float *p_h0a, *p_h0b, *p_h1a, *p_h1b;
    float *p_hs, *p_cur, *p_cur2, *p_u, *p_r;
    __half *p_wt;
    cudaGetSymbolAddress((void**)&p_h0a,  g_h0a);
    cudaGetSymbolAddress((void**)&p_h0b,  g_h0b);
    cudaGetSymbolAddress((void**)&p_h1a,  g_h1a);
    cudaGetSymbolAddress((void**)&p_h1b,  g_h1b);
    cudaGetSymbolAddress((void**)&p_hs,   g_hs);
    cudaGetSymbolAddress((void**)&p_cur,  g_cur);
    cudaGetSymbolAddress((void**)&p_cur2, g_cur2);
    cudaGetSymbolAddress((void**)&p_u,    g_u);
    cudaGetSymbolAddress((void**)&p_r,    g_r);
    cudaGetSymbolAddress((void**)&p_wt,   g_wt);

    const int EB = (EE + 255) / 256;
    const int PB = 128;
    const int GBK = NN / 8;   // gather blocks (8 nodes/block)

    for (int t = 0; t < TT; t++) {
        float* h0r = (t & 1) ? p_h0b : p_h0a;
        float* h0w = (t & 1) ? p_h0a : p_h0b;
        float* h1r = (t & 1) ? p_h1b : p_h1a;
        float* h1w = (t & 1) ? p_h1a : p_h1b;

        const int* src = ei + (size_t)t * 2 * EE;
        const int* dst = src + EE;
        const float* xin = x_seq + (size_t)t * NN * HH;

        // t=0 launch order: zero_deg(0), hist(1), prep(2), gemm(3) <- ncu idx 3
        zero_deg_kernel<<<128, 256>>>(NN);
        hist_kernel<<<EB, 256>>>(dst, EE);
        if (t == 0)
            prep_w_kernel<<<PB, 256>>>(W_in0, p_wt + OFF_WIN0, 128);
        gemm_tc(xin, nullptr, p_wt + OFF_WIN0,
                nullptr, nullptr, nullptr, nullptr, p_hs, nullptr, 128, EPI_NONE, 2, 0);
        scan_a_kernel<<<NBLK, 1024>>>(NN);
        scan_b_kernel<<<1, 64>>>(NN);
        scan_c_kernel<<<NBLK, 1024>>>(NN);
        fill_kernel<<<EB, 256>>>(src, dst, EE);
        if (t == 0) {
            zero_f_kernel<<<512, 256>>>(p_h0a, NN * HH);
            zero_f_kernel<<<512, 256>>>(p_h1a, NN * HH);
            prep_w_kernel<<<PB, 256>>>(W_h0,  p_wt + OFF_WH0,  128);
            prep_w_kernel<<<PB, 256>>>(Wu0,   p_wt + OFF_WU0,  256);
            prep_w_kernel<<<PB, 256>>>(Wr0,   p_wt + OFF_WR0,  256);
            prep_w_kernel<<<PB, 256>>>(Wc0,   p_wt + OFF_WC0,  256);
            prep_w_kernel<<<PB, 256>>>(W_in1, p_wt + OFF_WIN1, 128);
            prep_w_kernel<<<PB, 256>>>(W_h1,  p_wt + OFF_WH1,  128);
            prep_w_kernel<<<PB, 256>>>(Wu1,   p_wt + OFF_WU1,  256);
            prep_w_kernel<<<PB, 256>>>(Wr1,   p_wt + OFF_WR1,  256);
            prep_w_kernel<<<PB, 256>>>(Wc1,   p_wt + OFF_WC1,  256);
            prep_w_kernel<<<PB, 256>>>(W_out, p_wt + OFF_WOUT, 128);
        }

        // ---- layer 0 cell (state h0r -> h0w) ----
        gather_kernel<<<GBK, 256>>>(p_hs, b_in0, p_cur, 1);
        gemm_tc(p_cur, nullptr, p_wt + OFF_WH0,
                nullptr, nullptr, nullptr, nullptr, p_hs, nullptr, 128, EPI_NONE, 2, 0);
        gather_kernel<<<GBK, 256>>>(p_hs, b_h0, p_cur2, 0);
        // fused u|r: u -> p_u, r*h_prev -> p_r
        gemm_tc(p_cur2, h0r, p_wt + OFF_WU0,
                bu0, br0, nullptr, h0r, p_u, p_r, 256, EPI_SIG, 4, 1);
        gemm_tc(p_cur2, p_r, p_wt + OFF_WC0,
                bc0, nullptr, p_u, h0r, h0w, nullptr, 256, EPI_GRU, 2, 0);

        // ---- layer 1 cell (input h0w, state h1r -> h1w) ----
        gemm_tc(h0w, nullptr, p_wt + OFF_WIN1,
                nullptr, nullptr, nullptr, nullptr, p_hs, nullptr, 128, EPI_NONE, 2, 0);
        gather_kernel<<<GBK, 256>>>(p_hs, b_in1, p_cur, 1);
        gemm_tc(p_cur, nullptr, p_wt + OFF_WH1,
                nullptr, nullptr, nullptr, nullptr, p_hs, nullptr, 128, EPI_NONE, 2, 0);
        gather_kernel<<<GBK, 256>>>(p_hs, b_h1, p_cur2, 0);
        gemm_tc(p_cur2, h1r, p_wt + OFF_WU1,
                bu1, br1, nullptr, h1r, p_u, p_r, 256, EPI_SIG, 4, 1);
        gemm_tc(p_cur2, p_r, p_wt + OFF_WC1,
                bc1, nullptr, p_u, h1r, h1w, nullptr, 256, EPI_GRU, 2, 0);

        // ---- output projection ----
        gemm_tc(h1w, nullptr, p_wt + OFF_WOUT,
                b_out, nullptr, nullptr, nullptr, out + (size_t)t * NN * HH, nullptr,
                128, EPI_BIAS, 2, 0);
    }
}

// round 17
// speedup vs baseline: 1.3855x; 1.0505x over previous
#include <cuda_runtime.h>
#include <cuda_fp16.h>
#include <math.h>
#include <stdint.h>

#define NN 50000
#define TT 8
#define HH 128
#define EE 800000
#define NBLK 49   // scan blocks of 1024

// ---------------- scratch (device globals; no allocation allowed) ----------
__device__ __align__(16) float g_h0a[NN * HH];
__device__ __align__(16) float g_h0b[NN * HH];
__device__ __align__(16) float g_h1a[NN * HH];
__device__ __align__(16) float g_h1b[NN * HH];
__device__ __align__(16) float g_u[NN * HH];
// fp16 activation buffers
__device__ __align__(16) __half g_hs[NN * HH];
__device__ __align__(16) __half g_cur[NN * HH];
__device__ __align__(16) __half g_cur2[NN * HH];
__device__ __align__(16) __half g_rh[NN * HH];      // r*h_prev
__device__ __align__(16) __half g_h0ha[NN * HH];    // fp16 copies of h state
__device__ __align__(16) __half g_h0hb[NN * HH];
__device__ __align__(16) __half g_h1ha[NN * HH];
__device__ __align__(16) __half g_h1hb[NN * HH];
// CSR
__device__ int   g_deg[NN];
__device__ int   g_rowptr[NN + 1];
__device__ int   g_cursor[NN];
__device__ int   g_csrc[EE];
__device__ float g_dinv[NN];
__device__ int   g_bsum[64];
__device__ int   g_boff[64];

// transposed fp16 weights, [N rows, K cols]
#define WT_TOTAL 278528
__device__ __align__(16) __half g_wt[WT_TOTAL];

// WU/WR pairs contiguous: [Wu rows 0-127 | Wr rows 128-255], K=256
#define OFF_WIN0 0
#define OFF_WH0  16384
#define OFF_WU0  32768
#define OFF_WR0  65536
#define OFF_WC0  98304
#define OFF_WIN1 131072
#define OFF_WH1  147456
#define OFF_WU1  163840
#define OFF_WR1  196608
#define OFF_WC1  229376
#define OFF_WOUT 262144

// ---------------- warp-mma helpers (baseline PTX, no arch suffix) -----------
__device__ __forceinline__ uint32_t smem_u32(const void* p) {
    uint32_t a;
    asm("{ .reg .u64 t; cvta.to.shared.u64 t, %1; cvt.u32.u64 %0, t; }" : "=r"(a) : "l"(p));
    return a;
}
__device__ __forceinline__ void ldsm4(uint32_t& r0, uint32_t& r1, uint32_t& r2, uint32_t& r3,
                                      uint32_t addr) {
    asm volatile("ldmatrix.sync.aligned.m8n8.x4.shared.b16 {%0,%1,%2,%3}, [%4];"
                 : "=r"(r0), "=r"(r1), "=r"(r2), "=r"(r3) : "r"(addr));
}
__device__ __forceinline__ void mma_f16(float* d, const uint32_t* a, const uint32_t* b) {
    asm volatile(
        "mma.sync.aligned.m16n8k16.row.col.f32.f16.f16.f32 "
        "{%0,%1,%2,%3},{%4,%5,%6,%7},{%8,%9},{%0,%1,%2,%3};"
        : "+f"(d[0]), "+f"(d[1]), "+f"(d[2]), "+f"(d[3])
        : "r"(a[0]), "r"(a[1]), "r"(a[2]), "r"(a[3]), "r"(b[0]), "r"(b[1]));
}

// ---------------- small utility kernels ------------------------------------
__global__ void zero_f_kernel(float* p, int n) {
    for (int i = blockIdx.x * blockDim.x + threadIdx.x; i < n; i += gridDim.x * blockDim.x)
        p[i] = 0.0f;
}
__global__ void zero_deg_kernel(int n) {
    for (int i = blockIdx.x * blockDim.x + threadIdx.x; i < n; i += gridDim.x * blockDim.x)
        g_deg[i] = 0;
}
__global__ void hist_kernel(const int* __restrict__ dst, int e) {
    for (int i = blockIdx.x * blockDim.x + threadIdx.x; i < e; i += gridDim.x * blockDim.x)
        atomicAdd(&g_deg[dst[i]], 1);
}

// scan phase A
__global__ __launch_bounds__(1024) void scan_a_kernel(int n) {
    __shared__ int wsum[32];
    const int lane = threadIdx.x & 31;
    const int wid  = threadIdx.x >> 5;
    const int i = blockIdx.x * 1024 + threadIdx.x;
    int v = (i < n) ? g_deg[i] : 0;
    int incl = v;
    #pragma unroll
    for (int off = 1; off < 32; off <<= 1) {
        int t = __shfl_up_sync(0xffffffffu, incl, off);
        if (lane >= off) incl += t;
    }
    if (lane == 31) wsum[wid] = incl;
    __syncthreads();
    if (wid == 0) {
        int w = wsum[lane];
        #pragma unroll
        for (int off = 1; off < 32; off <<= 1) {
            int t = __shfl_up_sync(0xffffffffu, w, off);
            if (lane >= off) w += t;
        }
        wsum[lane] = w;
    }
    __syncthreads();
    int excl = (incl - v) + (wid > 0 ? wsum[wid - 1] : 0);
    if (i < n) {
        g_rowptr[i] = excl;
        g_dinv[i]   = rsqrtf((float)v + 1.0f);
    }
    if (threadIdx.x == 1023) g_bsum[blockIdx.x] = excl + v;
}
__global__ void scan_b_kernel(int n) {
    __shared__ int sh[64];
    const int tid = threadIdx.x;
    const int lane = tid & 31;
    const int w = tid >> 5;
    int v = (tid < NBLK) ? g_bsum[tid] : 0;
    int incl = v;
    #pragma unroll
    for (int off = 1; off < 32; off <<= 1) {
        int t = __shfl_up_sync(0xffffffffu, incl, off);
        if (lane >= off) incl += t;
    }
    if (lane == 31) sh[w] = incl;
    __syncthreads();
    int base = (w == 1) ? sh[0] : 0;
    incl += base;
    if (tid < NBLK) g_boff[tid] = incl - v;
    if (tid == NBLK - 1) g_rowptr[n] = incl;
}
__global__ __launch_bounds__(1024) void scan_c_kernel(int n) {
    const int i = blockIdx.x * 1024 + threadIdx.x;
    if (i < n) {
        int r = g_rowptr[i] + g_boff[blockIdx.x];
        g_rowptr[i] = r;
        g_cursor[i] = r;
    }
}
__global__ void fill_kernel(const int* __restrict__ src, const int* __restrict__ dst, int e) {
    for (int i = blockIdx.x * blockDim.x + threadIdx.x; i < e; i += gridDim.x * blockDim.x) {
        int slot = atomicAdd(&g_cursor[dst[i]], 1);
        g_csrc[slot] = src[i];
    }
}

// warp-per-node gather on fp16 rows: lane handles 4 features (uint2 = 4 halves)
__global__ __launch_bounds__(256) void gather_kernel(
    const __half* __restrict__ hs, const float* __restrict__ bias,
    __half* __restrict__ out, int relu) {
    const int wid = threadIdx.x >> 5;
    const int lane = threadIdx.x & 31;
    const int node = blockIdx.x * 8 + wid;
    const int beg = g_rowptr[node];
    const int end = g_rowptr[node + 1];
    const float dn = g_dinv[node];
    const uint2* hs2 = (const uint2*)hs;   // 32 uint2 per 128-half row
    const size_t fo = (size_t)node * 32 + lane;

    float4 acc;
    {
        uint2 q = hs2[fo];
        float2 a0 = __half22float2(*(const __half2*)&q.x);
        float2 a1 = __half22float2(*(const __half2*)&q.y);
        acc = make_float4(dn * a0.x, dn * a0.y, dn * a1.x, dn * a1.y);
    }
    int j = beg;
    for (; j + 4 <= end; j += 4) {
        int s0 = g_csrc[j], s1 = g_csrc[j + 1], s2 = g_csrc[j + 2], s3 = g_csrc[j + 3];
        float d0 = g_dinv[s0], d1 = g_dinv[s1], d2 = g_dinv[s2], d3 = g_dinv[s3];
        uint2 q0 = hs2[(size_t)s0 * 32 + lane];
        uint2 q1 = hs2[(size_t)s1 * 32 + lane];
        uint2 q2 = hs2[(size_t)s2 * 32 + lane];
        uint2 q3 = hs2[(size_t)s3 * 32 + lane];
        float2 v0a = __half22float2(*(const __half2*)&q0.x);
        float2 v0b = __half22float2(*(const __half2*)&q0.y);
        float2 v1a = __half22float2(*(const __half2*)&q1.x);
        float2 v1b = __half22float2(*(const __half2*)&q1.y);
        float2 v2a = __half22float2(*(const __half2*)&q2.x);
        float2 v2b = __half22float2(*(const __half2*)&q2.y);
        float2 v3a = __half22float2(*(const __half2*)&q3.x);
        float2 v3b = __half22float2(*(const __half2*)&q3.y);
        acc.x += d0 * v0a.x + d1 * v1a.x + d2 * v2a.x + d3 * v3a.x;
        acc.y += d0 * v0a.y + d1 * v1a.y + d2 * v2a.y + d3 * v3a.y;
        acc.z += d0 * v0b.x + d1 * v1b.x + d2 * v2b.x + d3 * v3b.x;
        acc.w += d0 * v0b.y + d1 * v1b.y + d2 * v2b.y + d3 * v3b.y;
    }
    for (; j < end; ++j) {
        int s = g_csrc[j];
        float d = g_dinv[s];
        uint2 q = hs2[(size_t)s * 32 + lane];
        float2 va = __half22float2(*(const __half2*)&q.x);
        float2 vb = __half22float2(*(const __half2*)&q.y);
        acc.x += d * va.x; acc.y += d * va.y; acc.z += d * vb.x; acc.w += d * vb.y;
    }
    float4 b = ((const float4*)bias)[lane];
    float r0 = dn * acc.x + b.x;
    float r1 = dn * acc.y + b.y;
    float r2 = dn * acc.z + b.z;
    float r3 = dn * acc.w + b.w;
    if (relu) {
        r0 = fmaxf(r0, 0.0f); r1 = fmaxf(r1, 0.0f);
        r2 = fmaxf(r2, 0.0f); r3 = fmaxf(r3, 0.0f);
    }
    __half2 h01 = __floats2half2_rn(r0, r1);
    __half2 h23 = __floats2half2_rn(r2, r3);
    uint2 o;
    o.x = *(uint32_t*)&h01;
    o.y = *(uint32_t*)&h23;
    ((uint2*)out)[fo] = o;
}

// weight prep: src [K,128] f32 row-major -> dst [128,K] fp16 (transposed)
__global__ void prep_w_kernel(const float* __restrict__ W,
                              __half* __restrict__ hi, int K) {
    int total = K * 128;
    for (int idx = blockIdx.x * blockDim.x + threadIdx.x; idx < total;
         idx += gridDim.x * blockDim.x) {
        int k = idx >> 7;
        int nn = idx & 127;
        hi[(size_t)nn * K + k] = __float2half_rn(W[idx]);
    }
}

// ---------------- tensor-core GEMM via mma.sync (single-pass fp16) ----------
// CONV=1: A1v is f32 [n,128] (win0 only). CONV=0: A1v/A2 are fp16 [n,128].
// Block tile 128(M) x 64(N), 8 warps of 32x32, 2 CTAs/SM.
#define EPI_NONE 0
#define EPI_SIG  1
#define EPI_GRU  2
#define EPI_BIAS 3

#define ROWB 80
#define SM_A   0
#define SM_B   (128 * ROWB)               // 10240
#define SM_TOT (128 * ROWB + 64 * ROWB)   // 15360

template <int CONV>
__global__ __launch_bounds__(256, 2) void gemm_mma_kernel(
    const void* __restrict__ A1v, const __half* __restrict__ A2,
    const __half* __restrict__ Bt,
    const float* __restrict__ bias, const float* __restrict__ bias2,
    const float* __restrict__ u, const float* __restrict__ hprev,
    float* __restrict__ outf, __half* __restrict__ outh,
    int n, int K, int epi, int split)
{
    extern __shared__ __align__(16) char smem[];
    const uint32_t sb = smem_u32(smem);
    const int tid = threadIdx.x;
    const int wid = tid >> 5;
    const int lane = tid & 31;
    const int row0 = blockIdx.x * 128;
    const int n0 = blockIdx.y * 64;
    const int wm = wid & 3;
    const int wn = wid >> 2;

    // CONV f32 staging: 1024 float4 slots, 4 per thread
    const int ar[4] = { (tid + 0) >> 3, (tid + 256) >> 3, (tid + 512) >> 3, (tid + 768) >> 3 };
    const int ac4 = (tid & 7) * 4;
    // fp16 A staging: 512 uint4 slots, 2 per thread
    const int par0 = tid >> 2;
    const int par1 = (tid >> 2) + 64;
    const int pac8 = (tid & 3) * 8;
    // B staging
    const int br_ = tid >> 2;
    const int bc8 = (tid & 3) * 8;

    float acc[2][4][4];
    #pragma unroll
    for (int i = 0; i < 2; i++)
        #pragma unroll
        for (int j = 0; j < 4; j++)
            #pragma unroll
            for (int q = 0; q < 4; q++) acc[i][j][q] = 0.0f;

    const int nc = K >> 5;
    float4 pa[4];
    uint4 pah0, pah1, pb;
    const uint4 z4 = make_uint4(0u, 0u, 0u, 0u);

    {
        if (CONV) {
            const float* Af = (const float*)A1v;
            #pragma unroll
            for (int it = 0; it < 4; it++) {
                int grow = row0 + ar[it];
                pa[it] = (grow < n) ? *(const float4*)(Af + (size_t)grow * 128 + ac4)
                                    : make_float4(0.f, 0.f, 0.f, 0.f);
            }
        } else {
            const __half* Ah = (const __half*)A1v;
            int g0 = row0 + par0, g1 = row0 + par1;
            pah0 = (g0 < n) ? *(const uint4*)(Ah + (size_t)g0 * 128 + pac8) : z4;
            pah1 = (g1 < n) ? *(const uint4*)(Ah + (size_t)g1 * 128 + pac8) : z4;
        }
        size_t goff = (size_t)(n0 + br_) * K + bc8;
        pb = *(const uint4*)(Bt + goff);
    }

    for (int c = 0; c < nc; c++) {
        if (CONV) {
            #pragma unroll
            for (int it = 0; it < 4; it++) {
                float4 v = pa[it];
                __half h0 = __float2half_rn(v.x);
                __half h1 = __float2half_rn(v.y);
                __half h2 = __float2half_rn(v.z);
                __half h3 = __float2half_rn(v.w);
                uint32_t hA = (uint32_t)__half_as_ushort(h0) |
                              ((uint32_t)__half_as_ushort(h1) << 16);
                uint32_t hB = (uint32_t)__half_as_ushort(h2) |
                              ((uint32_t)__half_as_ushort(h3) << 16);
                uint32_t off = ar[it] * ROWB + ac4 * 2;
                *(uint2*)(smem + SM_A + off) = make_uint2(hA, hB);
            }
        } else {
            *(uint4*)(smem + SM_A + par0 * ROWB + pac8 * 2) = pah0;
            *(uint4*)(smem + SM_A + par1 * ROWB + pac8 * 2) = pah1;
        }
        {
            uint32_t off = br_ * ROWB + bc8 * 2;
            *(uint4*)(smem + SM_B + off) = pb;
        }
        __syncthreads();

        if (c + 1 < nc) {
            const int kn = (c + 1) * 32;
            if (CONV) {
                const float* Af = (const float*)A1v;
                #pragma unroll
                for (int it = 0; it < 4; it++) {
                    int grow = row0 + ar[it];
                    pa[it] = (grow < n)
                        ? *(const float4*)(Af + (size_t)grow * 128 + kn + ac4)
                        : make_float4(0.f, 0.f, 0.f, 0.f);
                }
            } else {
                const __half* Ah = (kn >= 128) ? A2 : (const __half*)A1v;
                const int kln = (kn >= 128) ? kn - 128 : kn;
                int g0 = row0 + par0, g1 = row0 + par1;
                pah0 = (g0 < n) ? *(const uint4*)(Ah + (size_t)g0 * 128 + kln + pac8) : z4;
                pah1 = (g1 < n) ? *(const uint4*)(Ah + (size_t)g1 * 128 + kln + pac8) : z4;
            }
            size_t goff = (size_t)(n0 + br_) * K + kn + bc8;
            pb = *(const uint4*)(Bt + goff);
        }

        #pragma unroll
        for (int ks = 0; ks < 2; ks++) {
            uint32_t ah[2][4];
            #pragma unroll
            for (int mt = 0; mt < 2; mt++) {
                uint32_t addr = sb + SM_A +
                    (uint32_t)(wm * 32 + mt * 16 + (lane & 15)) * ROWB +
                    ks * 32 + (lane >> 4) * 16;
                ldsm4(ah[mt][0], ah[mt][1], ah[mt][2], ah[mt][3], addr);
            }
            uint32_t bh0[4], bh1[4];
            {
                uint32_t baddr = sb + SM_B + (uint32_t)(wn * 32 + lane) * ROWB + ks * 32;
                ldsm4(bh0[0], bh0[1], bh0[2], bh0[3], baddr);
                ldsm4(bh1[0], bh1[1], bh1[2], bh1[3], baddr + 16);
            }
            #pragma unroll
            for (int mt = 0; mt < 2; mt++) {
                #pragma unroll
                for (int nt = 0; nt < 4; nt++) {
                    uint32_t bh[2] = {bh0[nt], bh1[nt]};
                    mma_f16(acc[mt][nt], ah[mt], bh);
                }
            }
        }
        __syncthreads();
    }

    // ---- epilogue ----
    const int urpart = split ? (int)(blockIdx.y >> 1) : 0;
    const float* biasX = (split && urpart) ? bias2 : bias;
    const int ybase = (blockIdx.y & 1) * 64;
    const int qrow = lane >> 2;
    const int qcol = (lane & 3) * 2;
    const int gc_base = ybase + wn * 32;
    #pragma unroll
    for (int mt = 0; mt < 2; mt++) {
        #pragma unroll
        for (int rs = 0; rs < 2; rs++) {
            int grow = row0 + wm * 32 + mt * 16 + rs * 8 + qrow;
            if (grow >= n) continue;
            size_t rbase = (size_t)grow * 128;
            #pragma unroll
            for (int nt = 0; nt < 4; nt++) {
                int gc = gc_base + nt * 8 + qcol;
                float v0 = acc[mt][nt][rs * 2];
                float v1 = acc[mt][nt][rs * 2 + 1];
                if (epi == EPI_NONE) {
                    __half2 h = __floats2half2_rn(v0, v1);
                    *(__half2*)(outh + rbase + gc) = h;
                } else if (epi == EPI_SIG) {
                    float s0 = 1.0f / (1.0f + expf(-(v0 + biasX[gc])));
                    float s1 = 1.0f / (1.0f + expf(-(v1 + biasX[gc + 1])));
                    if (!urpart) {
                        *(float2*)(outf + rbase + gc) = make_float2(s0, s1);
                    } else {
                        float2 hp = *(const float2*)(hprev + rbase + gc);
                        __half2 h = __floats2half2_rn(s0 * hp.x, s1 * hp.y);
                        *(__half2*)(outh + rbase + gc) = h;
                    }
                } else if (epi == EPI_GRU) {
                    float a0 = tanhf(v0 + biasX[gc]);
                    float a1 = tanhf(v1 + biasX[gc + 1]);
                    float2 hp = *(const float2*)(hprev + rbase + gc);
                    float2 uu = *(const float2*)(u + rbase + gc);
                    float r0 = hp.x + uu.x * (a0 - hp.x);
                    float r1 = hp.y + uu.y * (a1 - hp.y);
                    *(float2*)(outf + rbase + gc) = make_float2(r0, r1);
                    __half2 h = __floats2half2_rn(r0, r1);
                    *(__half2*)(outh + rbase + gc) = h;
                } else {
                    *(float2*)(outf + rbase + gc) =
                        make_float2(v0 + biasX[gc], v1 + biasX[gc + 1]);
                }
            }
        }
    }
}

// ---------------- driver ------------------------------------------------------
static inline void gemm_h(const __half* a1, const __half* a2, const __half* bt,
                          const float* bias, const float* bias2,
                          const float* u, const float* hprev,
                          float* outf, __half* outh, int K, int epi, int ny, int split) {
    dim3 grid((NN + 127) / 128, ny);
    gemm_mma_kernel<0><<<grid, 256, SM_TOT>>>(a1, a2, bt, bias, bias2,
                                              u, hprev, outf, outh, NN, K, epi, split);
}
static inline void gemm_f(const float* a1, const __half* bt, __half* outh) {
    dim3 grid((NN + 127) / 128, 2);
    gemm_mma_kernel<1><<<grid, 256, SM_TOT>>>(a1, nullptr, bt, nullptr, nullptr,
                                              nullptr, nullptr, nullptr, outh,
                                              NN, 128, EPI_NONE, 0);
}

extern "C" void kernel_launch(void* const* d_in, const int* in_sizes, int n_in,
                              void* d_out, int out_size) {
    const float* x_seq = (const float*)d_in[0];
    const int*   ei    = (const int*)d_in[1];
    const float* W_in0 = (const float*)d_in[2];
    const float* b_in0 = (const float*)d_in[3];
    const float* W_h0  = (const float*)d_in[4];
    const float* b_h0  = (const float*)d_in[5];
    const float* Wu0   = (const float*)d_in[6];
    const float* bu0   = (const float*)d_in[7];
    const float* Wr0   = (const float*)d_in[8];
    const float* br0   = (const float*)d_in[9];
    const float* Wc0   = (const float*)d_in[10];
    const float* bc0   = (const float*)d_in[11];
    const float* W_in1 = (const float*)d_in[12];
    const float* b_in1 = (const float*)d_in[13];
    const float* W_h1  = (const float*)d_in[14];
    const float* b_h1  = (const float*)d_in[15];
    const float* Wu1   = (const float*)d_in[16];
    const float* bu1   = (const float*)d_in[17];
    const float* Wr1   = (const float*)d_in[18];
    const float* br1   = (const float*)d_in[19];
    const float* Wc1   = (const float*)d_in[20];
    const float* bc1   = (const float*)d_in[21];
    const float* W_out = (const float*)d_in[22];
    const float* b_out = (const float*)d_in[23];
    float* out = (float*)d_out;

    float *p_h0a, *p_h0b, *p_h1a, *p_h1b, *p_u;
    __half *p_hs, *p_cur, *p_cur2, *p_rh;
    __half *p_h0ha, *p_h0hb, *p_h1ha, *p_h1hb, *p_wt;
    cudaGetSymbolAddress((void**)&p_h0a,  g_h0a);
    cudaGetSymbolAddress((void**)&p_h0b,  g_h0b);
    cudaGetSymbolAddress((void**)&p_h1a,  g_h1a);
    cudaGetSymbolAddress((void**)&p_h1b,  g_h1b);
    cudaGetSymbolAddress((void**)&p_u,    g_u);
    cudaGetSymbolAddress((void**)&p_hs,   g_hs);
    cudaGetSymbolAddress((void**)&p_cur,  g_cur);
    cudaGetSymbolAddress((void**)&p_cur2, g_cur2);
    cudaGetSymbolAddress((void**)&p_rh,   g_rh);
    cudaGetSymbolAddress((void**)&p_h0ha, g_h0ha);
    cudaGetSymbolAddress((void**)&p_h0hb, g_h0hb);
    cudaGetSymbolAddress((void**)&p_h1ha, g_h1ha);
    cudaGetSymbolAddress((void**)&p_h1hb, g_h1hb);
    cudaGetSymbolAddress((void**)&p_wt,   g_wt);

    const int EB = (EE + 255) / 256;
    const int PB = 128;
    const int GBK = NN / 8;

    for (int t = 0; t < TT; t++) {
        float* h0r = (t & 1) ? p_h0b : p_h0a;
        float* h0w = (t & 1) ? p_h0a : p_h0b;
        float* h1r = (t & 1) ? p_h1b : p_h1a;
        float* h1w = (t & 1) ? p_h1a : p_h1b;
        __half* h0rh = (t & 1) ? p_h0hb : p_h0ha;
        __half* h0wh = (t & 1) ? p_h0ha : p_h0hb;
        __half* h1rh = (t & 1) ? p_h1hb : p_h1ha;
        __half* h1wh = (t & 1) ? p_h1ha : p_h1hb;

        const int* src = ei + (size_t)t * 2 * EE;
        const int* dst = src + EE;
        const float* xin = x_seq + (size_t)t * NN * HH;

        // t=0 launch order: zero_deg(0), hist(1), prep(2), gemm(3) <- ncu idx 3
        zero_deg_kernel<<<128, 256>>>(NN);
        hist_kernel<<<EB, 256>>>(dst, EE);
        if (t == 0)
            prep_w_kernel<<<PB, 256>>>(W_in0, p_wt + OFF_WIN0, 128);
        gemm_f(xin, p_wt + OFF_WIN0, p_hs);
        scan_a_kernel<<<NBLK, 1024>>>(NN);
        scan_b_kernel<<<1, 64>>>(NN);
        scan_c_kernel<<<NBLK, 1024>>>(NN);
        fill_kernel<<<EB, 256>>>(src, dst, EE);
        if (t == 0) {
            zero_f_kernel<<<512, 256>>>(p_h0a, NN * HH);
            zero_f_kernel<<<512, 256>>>(p_h1a, NN * HH);
            zero_f_kernel<<<256, 256>>>((float*)p_h0ha, NN * HH / 2);
            zero_f_kernel<<<256, 256>>>((float*)p_h1ha, NN * HH / 2);
            prep_w_kernel<<<PB, 256>>>(W_h0,  p_wt + OFF_WH0,  128);
            prep_w_kernel<<<PB, 256>>>(Wu0,   p_wt + OFF_WU0,  256);
            prep_w_kernel<<<PB, 256>>>(Wr0,   p_wt + OFF_WR0,  256);
            prep_w_kernel<<<PB, 256>>>(Wc0,   p_wt + OFF_WC0,  256);
            prep_w_kernel<<<PB, 256>>>(W_in1, p_wt + OFF_WIN1, 128);
            prep_w_kernel<<<PB, 256>>>(W_h1,  p_wt + OFF_WH1,  128);
            prep_w_kernel<<<PB, 256>>>(Wu1,   p_wt + OFF_WU1,  256);
            prep_w_kernel<<<PB, 256>>>(Wr1,   p_wt + OFF_WR1,  256);
            prep_w_kernel<<<PB, 256>>>(Wc1,   p_wt + OFF_WC1,  256);
            prep_w_kernel<<<PB, 256>>>(W_out, p_wt + OFF_WOUT, 128);
        }

        // ---- layer 0 cell (state h0r/h0rh -> h0w/h0wh) ----
        gather_kernel<<<GBK, 256>>>(p_hs, b_in0, p_cur, 1);
        gemm_h(p_cur, nullptr, p_wt + OFF_WH0,
               nullptr, nullptr, nullptr, nullptr, nullptr, p_hs, 128, EPI_NONE, 2, 0);
        gather_kernel<<<GBK, 256>>>(p_hs, b_h0, p_cur2, 0);
        // fused u|r: u -> p_u (f32), r*h_prev -> p_rh (fp16)
        gemm_h(p_cur2, h0rh, p_wt + OFF_WU0,
               bu0, br0, nullptr, h0r, p_u, p_rh, 256, EPI_SIG, 4, 1);
        gemm_h(p_cur2, p_rh, p_wt + OFF_WC0,
               bc0, nullptr, p_u, h0r, h0w, h0wh, 256, EPI_GRU, 2, 0);

        // ---- layer 1 cell ----
        gemm_h(h0wh, nullptr, p_wt + OFF_WIN1,
               nullptr, nullptr, nullptr, nullptr, nullptr, p_hs, 128, EPI_NONE, 2, 0);
        gather_kernel<<<GBK, 256>>>(p_hs, b_in1, p_cur, 1);
        gemm_h(p_cur, nullptr, p_wt + OFF_WH1,
               nullptr, nullptr, nullptr, nullptr, nullptr, p_hs, 128, EPI_NONE, 2, 0);
        gather_kernel<<<GBK, 256>>>(p_hs, b_h1, p_cur2, 0);
        gemm_h(p_cur2, h1rh, p_wt + OFF_WU1,
               bu1, br1, nullptr, h1r, p_u, p_rh, 256, EPI_SIG, 4, 1);
        gemm_h(p_cur2, p_rh, p_wt + OFF_WC1,
               bc1, nullptr, p_u, h1r, h1w, h1wh, 256, EPI_GRU, 2, 0);

        // ---- output projection ----
        gemm_h(h1wh, nullptr, p_wt + OFF_WOUT,
               b_out, nullptr, nullptr, nullptr, out + (size_t)t * NN * HH, nullptr,
               128, EPI_BIAS, 2, 0);
    }
}